// round 1
// baseline (speedup 1.0000x reference)
#include <cuda_runtime.h>
#include <math.h>

#define NN 50000
#define NE 100000
#define NB 2048
#define D  64

// ---------------- scratch (device globals; no allocation allowed) -------------
__device__ float    g_h1[(size_t)NE * 128];     // edge-net hidden   (51.2 MB)
__device__ float    g_ew[(size_t)NE * 4096];    // edge weight mats  (1.64 GB)
__device__ float    g_out[NN * D];              // node state (h == out)
__device__ float    g_agg[NN * D];              // message accumulator
__device__ float    g_invdeg[NN];
__device__ float    g_e[NN];
__device__ float    g_a[NN];
__device__ unsigned g_segmax[NB];
__device__ float    g_denom[NB];
__device__ float    g_r[NB * D];
__device__ float    g_qstar[NB * 2 * D];
__device__ float    g_hh[NB * D];
__device__ float    g_cc[NB * D];

__device__ __forceinline__ float sigmoidf_(float x) { return 1.f / (1.f + expf(-x)); }

// monotonic float<->uint key for atomicMax on floats
__device__ __forceinline__ unsigned fkey(float f) {
    unsigned b = __float_as_uint(f);
    return (b & 0x80000000u) ? ~b : (b | 0x80000000u);
}
__device__ __forceinline__ float fdec(unsigned k) {
    unsigned b = (k & 0x80000000u) ? (k ^ 0x80000000u) : ~k;
    return __uint_as_float(b);
}

// ---------------- zero kernels ----------------
__global__ void k_zero_invdeg() {
    int i = blockIdx.x * 256 + threadIdx.x;
    if (i < NN) g_invdeg[i] = 0.f;
}
__global__ void k_zero_agg() {
    int i = blockIdx.x * 256 + threadIdx.x;  // grid exactly NN*D/256
    g_agg[i] = 0.f;
}
__global__ void k_zero_s2s() {
    int i = blockIdx.x * 256 + threadIdx.x;  // grid covers NB*256
    if (i < NB * 128) g_qstar[i] = 0.f;
    else if (i < NB * 192) g_hh[i - NB * 128] = 0.f;
    else g_cc[i - NB * 192] = 0.f;
}
__global__ void k_zero_att() {
    int i = blockIdx.x * 256 + threadIdx.x;  // covers NB*66
    if (i < NB) { g_denom[i] = 0.f; g_segmax[i] = 0u; }
    else if (i < NB + NB * 64) g_r[i - NB] = 0.f;
}

// ---------------- lin0 + relu ----------------
__global__ void k_lin0(const float* __restrict__ x, const float* __restrict__ w,
                       const float* __restrict__ b) {
    __shared__ float xs[4][14];
    int g = threadIdx.x >> 6, o = threadIdx.x & 63;
    int n = blockIdx.x * 4 + g;
    if (o < 14) xs[g][o] = x[n * 14 + o];
    __syncthreads();
    float acc = b[o];
#pragma unroll
    for (int j = 0; j < 14; j++) acc += xs[g][j] * w[o * 14 + j];
    g_out[n * D + o] = fmaxf(acc, 0.f);
}

// ---------------- degree ----------------
__global__ void k_deg(const int* __restrict__ ei) {
    int e = blockIdx.x * 256 + threadIdx.x;
    if (e < NE) atomicAdd(&g_invdeg[ei[NE + e]], 1.f);
}
__global__ void k_deg_fin() {
    int n = blockIdx.x * 256 + threadIdx.x;
    if (n < NN) g_invdeg[n] = 1.f / fmaxf(g_invdeg[n], 1.f);
}

// ---------------- edge net layer 1 ----------------
__global__ void k_edge1(const float* __restrict__ ea, const float* __restrict__ w1,
                        const float* __restrict__ b1) {
    int k = threadIdx.x & 127;
    int e = blockIdx.x * 2 + (threadIdx.x >> 7);
    float a0 = ea[e * 4 + 0], a1 = ea[e * 4 + 1], a2 = ea[e * 4 + 2], a3 = ea[e * 4 + 3];
    float acc = b1[k] + a0 * w1[k * 4 + 0] + a1 * w1[k * 4 + 1] +
                a2 * w1[k * 4 + 2] + a3 * w1[k * 4 + 3];
    g_h1[(size_t)e * 128 + k] = fmaxf(acc, 0.f);
}

// ---------------- big GEMM: ew = h1 @ W2^T + b2  (M=1e5, N=4096, K=128) ------
// 128x128 tile, full K in SMEM (k-major, pad 132), 8x8 register tiles.
__global__ void __launch_bounds__(256, 1)
k_gemm2(const float* __restrict__ Bw, const float* __restrict__ b2) {
    extern __shared__ float sm[];
    float* As = sm;              // [128 k][132]
    float* Bs = sm + 128 * 132;  // [128 k][132]
    const int tid = threadIdx.x;
    const int m0 = blockIdx.y * 128, n0 = blockIdx.x * 128;
    {
        int r = tid & 127;
        bool isA = tid < 128;
        const float* src = isA ? (g_h1 + (size_t)(m0 + r) * 128)
                               : (Bw + (size_t)(n0 + r) * 128);
        float* dst = isA ? As : Bs;
        bool valid = (!isA) || (m0 + r < NE);
        const float4* s4 = reinterpret_cast<const float4*>(src);
#pragma unroll
        for (int kv = 0; kv < 32; kv++) {
            float4 v = valid ? s4[kv] : make_float4(0.f, 0.f, 0.f, 0.f);
            dst[(kv * 4 + 0) * 132 + r] = v.x;
            dst[(kv * 4 + 1) * 132 + r] = v.y;
            dst[(kv * 4 + 2) * 132 + r] = v.z;
            dst[(kv * 4 + 3) * 132 + r] = v.w;
        }
    }
    __syncthreads();
    const int tx = tid & 15, ty = tid >> 4;
    float acc[8][8];
#pragma unroll
    for (int i = 0; i < 8; i++)
#pragma unroll
        for (int j = 0; j < 8; j++) acc[i][j] = 0.f;

#pragma unroll 8
    for (int k = 0; k < 128; k++) {
        float4 a0 = *(const float4*)&As[k * 132 + ty * 8];
        float4 a1 = *(const float4*)&As[k * 132 + ty * 8 + 4];
        float4 b0 = *(const float4*)&Bs[k * 132 + tx * 8];
        float4 b1 = *(const float4*)&Bs[k * 132 + tx * 8 + 4];
        float av[8] = {a0.x, a0.y, a0.z, a0.w, a1.x, a1.y, a1.z, a1.w};
        float bv[8] = {b0.x, b0.y, b0.z, b0.w, b1.x, b1.y, b1.z, b1.w};
#pragma unroll
        for (int i = 0; i < 8; i++)
#pragma unroll
            for (int j = 0; j < 8; j++) acc[i][j] += av[i] * bv[j];
    }
    float bb[8];
#pragma unroll
    for (int j = 0; j < 8; j++) bb[j] = b2[n0 + tx * 8 + j];
#pragma unroll
    for (int i = 0; i < 8; i++) {
        int m = m0 + ty * 8 + i;
        if (m < NE) {
            float* cp = g_ew + (size_t)m * 4096 + n0 + tx * 8;
            float4 o0 = make_float4(acc[i][0] + bb[0], acc[i][1] + bb[1],
                                    acc[i][2] + bb[2], acc[i][3] + bb[3]);
            float4 o1 = make_float4(acc[i][4] + bb[4], acc[i][5] + bb[5],
                                    acc[i][6] + bb[6], acc[i][7] + bb[7]);
            *(float4*)cp = o0;
            *(float4*)(cp + 4) = o1;
        }
    }
}

// ---------------- per-edge matvec + scatter ----------------
__global__ void k_msg(const int* __restrict__ ei) {
    __shared__ float so[4][64];
    int g = threadIdx.x >> 6, o = threadIdx.x & 63;
    int e = blockIdx.x * 4 + g;
    int s = ei[e], d = ei[NE + e];
    so[g][o] = g_out[s * D + o];
    __syncthreads();
    const float* ewp = g_ew + (size_t)e * 4096 + o;
    float acc = 0.f;
#pragma unroll
    for (int i = 0; i < 64; i++) acc += so[g][i] * __ldg(ewp + i * 64);
    atomicAdd(&g_agg[d * D + o], acc);
}

// ---------------- fused conv_root + GRU ----------------
__global__ void k_node(const float* __restrict__ root, const float* __restrict__ cbias,
                       const float* __restrict__ wih, const float* __restrict__ whh,
                       const float* __restrict__ bih, const float* __restrict__ bhh) {
    extern __shared__ float sm[];
    float* root_s = sm;                 // 4096           [i*64+o]
    float* wih_s  = sm + 4096;          // 192*65 padded
    float* whh_s  = wih_s + 192 * 65;   // 192*65 padded
    float* cb_s   = whh_s + 192 * 65;   // 64
    float* bih_s  = cb_s + 64;          // 192
    float* bhh_s  = bih_s + 192;        // 192
    float* orow   = bhh_s + 192;        // 4*64
    float* mrow   = orow + 256;         // 4*64
    int tid = threadIdx.x;
    for (int i = tid; i < 4096; i += 256) root_s[i] = root[i];
    for (int i = tid; i < 192 * 64; i += 256) {
        int rr = i >> 6, cc = i & 63;
        wih_s[rr * 65 + cc] = wih[i];
        whh_s[rr * 65 + cc] = whh[i];
    }
    if (tid < 64) cb_s[tid] = cbias[tid];
    if (tid < 192) { bih_s[tid] = bih[tid]; bhh_s[tid] = bhh[tid]; }
    __syncthreads();
    int g = tid >> 6, o = tid & 63;
    for (int base = blockIdx.x * 4; base < NN; base += gridDim.x * 4) {
        int n = base + g;
        bool valid = n < NN;
        float h = valid ? g_out[n * D + o] : 0.f;
        orow[g * 64 + o] = h;
        __syncthreads();
        float m = cb_s[o];
        if (valid) m += g_agg[n * D + o] * g_invdeg[n];
#pragma unroll 16
        for (int i = 0; i < 64; i++) m += orow[g * 64 + i] * root_s[i * 64 + o];
        m = fmaxf(m, 0.f);
        mrow[g * 64 + o] = m;
        __syncthreads();
        float gi0 = bih_s[o], gi1 = bih_s[64 + o], gi2 = bih_s[128 + o];
        float gh0 = bhh_s[o], gh1 = bhh_s[64 + o], gh2 = bhh_s[128 + o];
        const float* w0 = wih_s + o * 65;
        const float* w1 = wih_s + (64 + o) * 65;
        const float* w2 = wih_s + (128 + o) * 65;
        const float* v0 = whh_s + o * 65;
        const float* v1 = whh_s + (64 + o) * 65;
        const float* v2 = whh_s + (128 + o) * 65;
#pragma unroll 8
        for (int i = 0; i < 64; i++) {
            float mi = mrow[g * 64 + i], hi = orow[g * 64 + i];
            gi0 += mi * w0[i]; gi1 += mi * w1[i]; gi2 += mi * w2[i];
            gh0 += hi * v0[i]; gh1 += hi * v1[i]; gh2 += hi * v2[i];
        }
        float r  = sigmoidf_(gi0 + gh0);
        float z  = sigmoidf_(gi1 + gh1);
        float nn = tanhf(gi2 + r * gh2);
        float hn = (1.f - z) * nn + z * h;
        __syncthreads();
        if (valid) g_out[n * D + o] = hn;
    }
}

// ---------------- Set2Set LSTM cell ----------------
__global__ void k_lstm(const float* __restrict__ wih, const float* __restrict__ whh,
                       const float* __restrict__ bih, const float* __restrict__ bhh) {
    extern __shared__ float sm[];
    float* wih_s = sm;                   // 256*129 padded
    float* whh_s = wih_s + 256 * 129;    // 256*65 padded
    float* qs    = whh_s + 256 * 65;     // 128
    float* hs    = qs + 128;             // 64
    float* gsh   = hs + 64;              // 256
    int tid = threadIdx.x;
    for (int i = tid; i < 256 * 128; i += 256) {
        int rr = i >> 7, cc = i & 127;
        wih_s[rr * 129 + cc] = wih[i];
    }
    for (int i = tid; i < 256 * 64; i += 256) {
        int rr = i >> 6, cc = i & 63;
        whh_s[rr * 65 + cc] = whh[i];
    }
    float bsum = bih[tid] + bhh[tid];
    __syncthreads();
    for (int it = 0; it < 8; it++) {
        int b = blockIdx.x + 256 * it;
        if (tid < 128) qs[tid] = g_qstar[b * 128 + tid];
        if (tid < 64)  hs[tid] = g_hh[b * 64 + tid];
        __syncthreads();
        float acc = bsum;
        const float* wr = wih_s + tid * 129;
#pragma unroll 16
        for (int i = 0; i < 128; i++) acc += qs[i] * wr[i];
        const float* vr = whh_s + tid * 65;
#pragma unroll 16
        for (int i = 0; i < 64; i++) acc += hs[i] * vr[i];
        gsh[tid] = acc;
        __syncthreads();
        if (tid < 64) {
            float ii = gsh[tid], ff = gsh[64 + tid], gg = gsh[128 + tid], oo = gsh[192 + tid];
            float c  = sigmoidf_(ff) * g_cc[b * 64 + tid] + sigmoidf_(ii) * tanhf(gg);
            float h2 = sigmoidf_(oo) * tanhf(c);
            g_cc[b * 64 + tid] = c;
            g_hh[b * 64 + tid] = h2;
        }
        __syncthreads();
    }
}

// ---------------- attention: scores + segment max ----------------
__global__ void k_att1(const int* __restrict__ batch) {
    int n = blockIdx.x * 8 + (threadIdx.x >> 5);
    int lane = threadIdx.x & 31;
    int b = batch[n];
    float v = g_out[n * D + lane] * g_hh[b * D + lane] +
              g_out[n * D + lane + 32] * g_hh[b * D + lane + 32];
#pragma unroll
    for (int off = 16; off; off >>= 1) v += __shfl_xor_sync(0xffffffffu, v, off);
    if (lane == 0) {
        g_e[n] = v;
        atomicMax(&g_segmax[b], fkey(v));
    }
}
__global__ void k_att2(const int* __restrict__ batch) {
    int n = blockIdx.x * 256 + threadIdx.x;
    if (n < NN) {
        int b = batch[n];
        float a = expf(g_e[n] - fdec(g_segmax[b]));
        g_a[n] = a;
        atomicAdd(&g_denom[b], a);
    }
}
__global__ void k_att3(const int* __restrict__ batch) {
    int g = threadIdx.x >> 6, o = threadIdx.x & 63;
    int n = blockIdx.x * 4 + g;
    int b = batch[n];
    float coeff = g_a[n] / (g_denom[b] + 1e-16f);
    atomicAdd(&g_r[b * D + o], coeff * g_out[n * D + o]);
}
__global__ void k_qstar() {
    int idx = blockIdx.x * 256 + threadIdx.x;
    int b = idx >> 7, t = idx & 127;
    g_qstar[idx] = (t < 64) ? g_hh[b * 64 + t] : g_r[b * 64 + t - 64];
}

// ---------------- output MLP ----------------
__global__ void k_final(const float* __restrict__ l1w, const float* __restrict__ l1b,
                        const float* __restrict__ l2w, const float* __restrict__ l2b,
                        float* __restrict__ y) {
    __shared__ float qs[128];
    __shared__ float y1[64];
    int b = blockIdx.x, tid = threadIdx.x;
    qs[tid] = g_qstar[b * 128 + tid];
    __syncthreads();
    if (tid < 64) {
        float acc = l1b[tid];
        const float* wr = l1w + tid * 128;
#pragma unroll 16
        for (int i = 0; i < 128; i++) acc += qs[i] * wr[i];
        y1[tid] = fmaxf(acc, 0.f) * l2w[tid];
    }
    __syncthreads();
    if (tid < 32) {
        float v = y1[tid] + y1[tid + 32];
#pragma unroll
        for (int off = 16; off; off >>= 1) v += __shfl_xor_sync(0xffffffffu, v, off);
        if (tid == 0) y[b] = v + l2b[0];
    }
}

// ---------------- launcher ----------------
extern "C" void kernel_launch(void* const* d_in, const int* in_sizes, int n_in,
                              void* d_out, int out_size) {
    const float* x        = (const float*)d_in[0];
    const int*   ei       = (const int*)d_in[1];
    const float* ea       = (const float*)d_in[2];
    const int*   batch    = (const int*)d_in[3];
    const float* lin0_w   = (const float*)d_in[4];
    const float* lin0_b   = (const float*)d_in[5];
    const float* nn_w1    = (const float*)d_in[6];
    const float* nn_b1    = (const float*)d_in[7];
    const float* nn_w2    = (const float*)d_in[8];
    const float* nn_b2    = (const float*)d_in[9];
    const float* conv_root= (const float*)d_in[10];
    const float* conv_bias= (const float*)d_in[11];
    const float* gwih     = (const float*)d_in[12];
    const float* gwhh     = (const float*)d_in[13];
    const float* gbih     = (const float*)d_in[14];
    const float* gbhh     = (const float*)d_in[15];
    const float* swih     = (const float*)d_in[16];
    const float* swhh     = (const float*)d_in[17];
    const float* sbih     = (const float*)d_in[18];
    const float* sbhh     = (const float*)d_in[19];
    const float* l1w      = (const float*)d_in[20];
    const float* l1b      = (const float*)d_in[21];
    const float* l2w      = (const float*)d_in[22];
    const float* l2b      = (const float*)d_in[23];
    float* yout = (float*)d_out;

    const int SMEM_GEMM2 = 2 * 128 * 132 * 4;                              // 135168
    const int SMEM_NODE  = (4096 + 2 * 192 * 65 + 64 + 192 + 192 + 512) * 4; // 120064
    const int SMEM_LSTM  = (256 * 129 + 256 * 65 + 128 + 64 + 256) * 4;   // 200448
    cudaFuncSetAttribute(k_gemm2, cudaFuncAttributeMaxDynamicSharedMemorySize, SMEM_GEMM2);
    cudaFuncSetAttribute(k_node,  cudaFuncAttributeMaxDynamicSharedMemorySize, SMEM_NODE);
    cudaFuncSetAttribute(k_lstm,  cudaFuncAttributeMaxDynamicSharedMemorySize, SMEM_LSTM);

    // 1) node embedding
    k_lin0<<<NN / 4, 256>>>(x, lin0_w, lin0_b);
    // 2) degrees
    k_zero_invdeg<<<(NN + 255) / 256, 256>>>();
    k_deg<<<(NE + 255) / 256, 256>>>(ei);
    k_deg_fin<<<(NN + 255) / 256, 256>>>();
    // 3) edge network
    k_edge1<<<NE / 2, 256>>>(ea, nn_w1, nn_b1);
    k_gemm2<<<dim3(32, (NE + 127) / 128), 256, SMEM_GEMM2>>>(nn_w2, nn_b2);
    // 4) 3 rounds of message passing + GRU
    for (int t = 0; t < 3; t++) {
        k_zero_agg<<<NN * D / 256, 256>>>();
        k_msg<<<NE / 4, 256>>>(ei);
        k_node<<<592, 256, SMEM_NODE>>>(conv_root, conv_bias, gwih, gwhh, gbih, gbhh);
    }
    // 5) Set2Set
    k_zero_s2s<<<NB, 256>>>();
    for (int s = 0; s < 3; s++) {
        k_lstm<<<256, 256, SMEM_LSTM>>>(swih, swhh, sbih, sbhh);
        k_zero_att<<<(NB * 66 + 255) / 256, 256>>>();
        k_att1<<<NN / 8, 256>>>(batch);
        k_att2<<<(NN + 255) / 256, 256>>>(batch);
        k_att3<<<NN / 4, 256>>>(batch);
        k_qstar<<<NB * 128 / 256, 256>>>();
    }
    // 6) readout MLP
    k_final<<<NB, 128>>>(l1w, l1b, l2w, l2b, yout);
}

// round 3
// speedup vs baseline: 1.3107x; 1.3107x over previous
#include <cuda_runtime.h>
#include <cuda_bf16.h>
#include <math.h>
#include <stdint.h>

#define NN 50000
#define NE 100000
#define NB 2048
#define D  64

// ---------------- scratch (device globals; no allocation allowed) -------------
__device__ __align__(16) __nv_bfloat16 g_h1_hi[(size_t)NE * 128];
__device__ __align__(16) __nv_bfloat16 g_h1_lo[(size_t)NE * 128];
__device__ __align__(16) __nv_bfloat16 g_w2_hi[(size_t)4096 * 128];
__device__ __align__(16) __nv_bfloat16 g_w2_lo[(size_t)4096 * 128];
__device__ float    g_ew[(size_t)NE * 4096];    // edge weight mats  (1.64 GB)
__device__ float    g_out[NN * D];              // node state (h == out)
__device__ float    g_agg[NN * D];              // message accumulator
__device__ float    g_invdeg[NN];
__device__ float    g_e[NN];
__device__ float    g_a[NN];
__device__ unsigned g_segmax[NB];
__device__ float    g_denom[NB];
__device__ float    g_r[NB * D];
__device__ float    g_qstar[NB * 2 * D];
__device__ float    g_hh[NB * D];
__device__ float    g_cc[NB * D];

__device__ __forceinline__ float sigmoidf_(float x) { return 1.f / (1.f + expf(-x)); }

__device__ __forceinline__ unsigned fkey(float f) {
    unsigned b = __float_as_uint(f);
    return (b & 0x80000000u) ? ~b : (b | 0x80000000u);
}
__device__ __forceinline__ float fdec(unsigned k) {
    unsigned b = (k & 0x80000000u) ? (k ^ 0x80000000u) : ~k;
    return __uint_as_float(b);
}

// ---------------- zero kernels ----------------
__global__ void k_zero_invdeg() {
    int i = blockIdx.x * 256 + threadIdx.x;
    if (i < NN) g_invdeg[i] = 0.f;
}
__global__ void k_zero_agg() {
    int i = blockIdx.x * 256 + threadIdx.x;
    g_agg[i] = 0.f;
}
__global__ void k_zero_s2s() {
    int i = blockIdx.x * 256 + threadIdx.x;
    if (i < NB * 128) g_qstar[i] = 0.f;
    else if (i < NB * 192) g_hh[i - NB * 128] = 0.f;
    else g_cc[i - NB * 192] = 0.f;
}
__global__ void k_zero_att() {
    int i = blockIdx.x * 256 + threadIdx.x;
    if (i < NB) { g_denom[i] = 0.f; g_segmax[i] = 0u; }
    else if (i < NB + NB * 64) g_r[i - NB] = 0.f;
}

// ---------------- lin0 + relu ----------------
__global__ void k_lin0(const float* __restrict__ x, const float* __restrict__ w,
                       const float* __restrict__ b) {
    __shared__ float xs[4][14];
    int g = threadIdx.x >> 6, o = threadIdx.x & 63;
    int n = blockIdx.x * 4 + g;
    if (o < 14) xs[g][o] = x[n * 14 + o];
    __syncthreads();
    float acc = b[o];
#pragma unroll
    for (int j = 0; j < 14; j++) acc += xs[g][j] * w[o * 14 + j];
    g_out[n * D + o] = fmaxf(acc, 0.f);
}

// ---------------- degree ----------------
__global__ void k_deg(const int* __restrict__ ei) {
    int e = blockIdx.x * 256 + threadIdx.x;
    if (e < NE) atomicAdd(&g_invdeg[ei[NE + e]], 1.f);
}
__global__ void k_deg_fin() {
    int n = blockIdx.x * 256 + threadIdx.x;
    if (n < NN) g_invdeg[n] = 1.f / fmaxf(g_invdeg[n], 1.f);
}

// ---------------- edge net layer 1 (writes split bf16) ----------------
__global__ void k_edge1(const float* __restrict__ ea, const float* __restrict__ w1,
                        const float* __restrict__ b1) {
    int k = threadIdx.x & 127;
    int e = blockIdx.x * 2 + (threadIdx.x >> 7);
    float a0 = ea[e * 4 + 0], a1 = ea[e * 4 + 1], a2 = ea[e * 4 + 2], a3 = ea[e * 4 + 3];
    float acc = b1[k] + a0 * w1[k * 4 + 0] + a1 * w1[k * 4 + 1] +
                a2 * w1[k * 4 + 2] + a3 * w1[k * 4 + 3];
    acc = fmaxf(acc, 0.f);
    __nv_bfloat16 hi = __float2bfloat16(acc);
    size_t idx = (size_t)e * 128 + k;
    g_h1_hi[idx] = hi;
    g_h1_lo[idx] = __float2bfloat16(acc - __bfloat162float(hi));
}

// ---------------- W2 fp32 -> bf16 hi/lo split ----------------
__global__ void k_w2conv(const float* __restrict__ w2) {
    int i = blockIdx.x * 256 + threadIdx.x;  // covers 4096*128
    float v = w2[i];
    __nv_bfloat16 hi = __float2bfloat16(v);
    g_w2_hi[i] = hi;
    g_w2_lo[i] = __float2bfloat16(v - __bfloat162float(hi));
}

// ---------------- HMMA helper ----------------
__device__ __forceinline__ void mma_bf16(float* c, const uint32_t* a,
                                         uint32_t b0, uint32_t b1) {
    asm volatile(
        "mma.sync.aligned.m16n8k16.row.col.f32.bf16.bf16.f32 "
        "{%0,%1,%2,%3}, {%4,%5,%6,%7}, {%8,%9}, {%0,%1,%2,%3};"
        : "+f"(c[0]), "+f"(c[1]), "+f"(c[2]), "+f"(c[3])
        : "r"(a[0]), "r"(a[1]), "r"(a[2]), "r"(a[3]), "r"(b0), "r"(b1));
}

// ---------------- big GEMM on HMMA: ew = h1 @ W2^T + b2 ----------------
// M=1e5 (pad 128), N=4096, K=128. Split-bf16 x3 passes, fp32 accum.
// SMEM word layout: [row][68 words], word = 2 bf16 (k-contiguous).
#define LDW 68
__global__ void __launch_bounds__(256, 1)
k_gemm_hmma(const float* __restrict__ b2) {
    extern __shared__ uint32_t sw[];
    uint32_t* A_HI = sw;
    uint32_t* A_LO = A_HI + 128 * LDW;
    uint32_t* B_HI = A_LO + 128 * LDW;
    uint32_t* B_LO = B_HI + 128 * LDW;
    const int tid = threadIdx.x;
    const int m0 = blockIdx.y * 128, n0 = blockIdx.x * 128;

    // ---- load tiles: threads 0-127 -> A row tid; 128-255 -> B row tid-128
    {
        int r = tid & 127;
        bool isA = tid < 128;
        const uint4 *sh, *sl;
        uint32_t *dh, *dl;
        bool valid = true;
        if (isA) {
            int m = m0 + r;
            valid = m < NE;
            sh = (const uint4*)(g_h1_hi + (size_t)m * 128);
            sl = (const uint4*)(g_h1_lo + (size_t)m * 128);
            dh = A_HI + r * LDW; dl = A_LO + r * LDW;
        } else {
            int n = n0 + r;
            sh = (const uint4*)(g_w2_hi + (size_t)n * 128);
            sl = (const uint4*)(g_w2_lo + (size_t)n * 128);
            dh = B_HI + r * LDW; dl = B_LO + r * LDW;
        }
#pragma unroll
        for (int kc = 0; kc < 16; kc++) {
            uint4 vh = valid ? sh[kc] : make_uint4(0u, 0u, 0u, 0u);
            uint4 vl = valid ? sl[kc] : make_uint4(0u, 0u, 0u, 0u);
            *(uint4*)(dh + kc * 4) = vh;
            *(uint4*)(dl + kc * 4) = vl;
        }
    }
    __syncthreads();

    const int wid = tid >> 5, lane = tid & 31;
    const int warpM = wid >> 1, warpN = wid & 1;
    const int g = lane >> 2, tg = lane & 3;

    float c[2][8][4];
#pragma unroll
    for (int mi = 0; mi < 2; mi++)
#pragma unroll
        for (int ni = 0; ni < 8; ni++)
#pragma unroll
            for (int q = 0; q < 4; q++) c[mi][ni][q] = 0.f;

    const uint32_t* Apass[3] = {A_HI, A_HI, A_LO};
    const uint32_t* Bpass[3] = {B_HI, B_LO, B_HI};

#pragma unroll
    for (int p = 0; p < 3; p++) {
        const uint32_t* As = Apass[p];
        const uint32_t* Bs = Bpass[p];
#pragma unroll
        for (int s = 0; s < 8; s++) {
            const int kw = s * 8 + tg;
            uint32_t a[2][4];
#pragma unroll
            for (int mi = 0; mi < 2; mi++) {
                const uint32_t* ar = As + (warpM * 32 + mi * 16 + g) * LDW;
                a[mi][0] = ar[kw];
                a[mi][1] = ar[8 * LDW + kw];
                a[mi][2] = ar[kw + 4];
                a[mi][3] = ar[8 * LDW + kw + 4];
            }
#pragma unroll
            for (int ni = 0; ni < 8; ni++) {
                const uint32_t* br = Bs + (warpN * 64 + ni * 8 + g) * LDW;
                uint32_t b0 = br[kw], b1 = br[kw + 4];
                mma_bf16(c[0][ni], a[0], b0, b1);
                mma_bf16(c[1][ni], a[1], b0, b1);
            }
        }
    }

    // ---- epilogue: bias + store
    {
        const int colbase = n0 + warpN * 64 + 2 * tg;
        float2 bias[8];
#pragma unroll
        for (int ni = 0; ni < 8; ni++)
            bias[ni] = *(const float2*)(b2 + colbase + ni * 8);
#pragma unroll
        for (int mi = 0; mi < 2; mi++) {
            int r0 = m0 + warpM * 32 + mi * 16 + g;
            if (r0 < NE) {
                float* rp = g_ew + (size_t)r0 * 4096 + colbase;
#pragma unroll
                for (int ni = 0; ni < 8; ni++) {
                    float2 v = make_float2(c[mi][ni][0] + bias[ni].x,
                                           c[mi][ni][1] + bias[ni].y);
                    *(float2*)(rp + ni * 8) = v;
                }
            }
            int r1 = r0 + 8;
            if (r1 < NE) {
                float* rp = g_ew + (size_t)r1 * 4096 + colbase;
#pragma unroll
                for (int ni = 0; ni < 8; ni++) {
                    float2 v = make_float2(c[mi][ni][2] + bias[ni].x,
                                           c[mi][ni][3] + bias[ni].y);
                    *(float2*)(rp + ni * 8) = v;
                }
            }
        }
    }
}

// ---------------- per-edge matvec + scatter ----------------
__global__ void k_msg(const int* __restrict__ ei) {
    __shared__ float so[4][64];
    int g = threadIdx.x >> 6, o = threadIdx.x & 63;
    int e = blockIdx.x * 4 + g;
    int s = ei[e], d = ei[NE + e];
    so[g][o] = g_out[s * D + o];
    __syncthreads();
    const float* ewp = g_ew + (size_t)e * 4096 + o;
    float acc = 0.f;
#pragma unroll
    for (int i = 0; i < 64; i++) acc += so[g][i] * __ldg(ewp + i * 64);
    atomicAdd(&g_agg[d * D + o], acc);
}

// ---------------- fused conv_root + GRU ----------------
__global__ void k_node(const float* __restrict__ root, const float* __restrict__ cbias,
                       const float* __restrict__ wih, const float* __restrict__ whh,
                       const float* __restrict__ bih, const float* __restrict__ bhh) {
    extern __shared__ float sm[];
    float* root_s = sm;                 // 4096
    float* wih_s  = sm + 4096;          // 192*65
    float* whh_s  = wih_s + 192 * 65;
    float* cb_s   = whh_s + 192 * 65;   // 64
    float* bih_s  = cb_s + 64;          // 192
    float* bhh_s  = bih_s + 192;        // 192
    float* orow   = bhh_s + 192;        // 4*64
    float* mrow   = orow + 256;         // 4*64
    int tid = threadIdx.x;
    for (int i = tid; i < 4096; i += 256) root_s[i] = root[i];
    for (int i = tid; i < 192 * 64; i += 256) {
        int rr = i >> 6, cc = i & 63;
        wih_s[rr * 65 + cc] = wih[i];
        whh_s[rr * 65 + cc] = whh[i];
    }
    if (tid < 64) cb_s[tid] = cbias[tid];
    if (tid < 192) { bih_s[tid] = bih[tid]; bhh_s[tid] = bhh[tid]; }
    __syncthreads();
    int g = tid >> 6, o = tid & 63;
    for (int base = blockIdx.x * 4; base < NN; base += gridDim.x * 4) {
        int n = base + g;
        bool valid = n < NN;
        float h = valid ? g_out[n * D + o] : 0.f;
        orow[g * 64 + o] = h;
        __syncthreads();
        float m = cb_s[o];
        if (valid) m += g_agg[n * D + o] * g_invdeg[n];
#pragma unroll 16
        for (int i = 0; i < 64; i++) m += orow[g * 64 + i] * root_s[i * 64 + o];
        m = fmaxf(m, 0.f);
        mrow[g * 64 + o] = m;
        __syncthreads();
        float gi0 = bih_s[o], gi1 = bih_s[64 + o], gi2 = bih_s[128 + o];
        float gh0 = bhh_s[o], gh1 = bhh_s[64 + o], gh2 = bhh_s[128 + o];
        const float* w0 = wih_s + o * 65;
        const float* w1 = wih_s + (64 + o) * 65;
        const float* w2 = wih_s + (128 + o) * 65;
        const float* v0 = whh_s + o * 65;
        const float* v1 = whh_s + (64 + o) * 65;
        const float* v2 = whh_s + (128 + o) * 65;
#pragma unroll 8
        for (int i = 0; i < 64; i++) {
            float mi = mrow[g * 64 + i], hi = orow[g * 64 + i];
            gi0 += mi * w0[i]; gi1 += mi * w1[i]; gi2 += mi * w2[i];
            gh0 += hi * v0[i]; gh1 += hi * v1[i]; gh2 += hi * v2[i];
        }
        float r  = sigmoidf_(gi0 + gh0);
        float z  = sigmoidf_(gi1 + gh1);
        float nn = tanhf(gi2 + r * gh2);
        float hn = (1.f - z) * nn + z * h;
        __syncthreads();
        if (valid) g_out[n * D + o] = hn;
    }
}

// ---------------- Set2Set LSTM cell ----------------
__global__ void k_lstm(const float* __restrict__ wih, const float* __restrict__ whh,
                       const float* __restrict__ bih, const float* __restrict__ bhh) {
    extern __shared__ float sm[];
    float* wih_s = sm;                   // 256*129
    float* whh_s = wih_s + 256 * 129;    // 256*65
    float* qs    = whh_s + 256 * 65;     // 128
    float* hs    = qs + 128;             // 64
    float* gsh   = hs + 64;              // 256
    int tid = threadIdx.x;
    for (int i = tid; i < 256 * 128; i += 256) {
        int rr = i >> 7, cc = i & 127;
        wih_s[rr * 129 + cc] = wih[i];
    }
    for (int i = tid; i < 256 * 64; i += 256) {
        int rr = i >> 6, cc = i & 63;
        whh_s[rr * 65 + cc] = whh[i];
    }
    float bsum = bih[tid] + bhh[tid];
    __syncthreads();
    for (int it = 0; it < 8; it++) {
        int b = blockIdx.x + 256 * it;
        if (tid < 128) qs[tid] = g_qstar[b * 128 + tid];
        if (tid < 64)  hs[tid] = g_hh[b * 64 + tid];
        __syncthreads();
        float acc = bsum;
        const float* wr = wih_s + tid * 129;
#pragma unroll 16
        for (int i = 0; i < 128; i++) acc += qs[i] * wr[i];
        const float* vr = whh_s + tid * 65;
#pragma unroll 16
        for (int i = 0; i < 64; i++) acc += hs[i] * vr[i];
        gsh[tid] = acc;
        __syncthreads();
        if (tid < 64) {
            float ii = gsh[tid], ff = gsh[64 + tid], gg = gsh[128 + tid], oo = gsh[192 + tid];
            float c  = sigmoidf_(ff) * g_cc[b * 64 + tid] + sigmoidf_(ii) * tanhf(gg);
            float h2 = sigmoidf_(oo) * tanhf(c);
            g_cc[b * 64 + tid] = c;
            g_hh[b * 64 + tid] = h2;
        }
        __syncthreads();
    }
}

// ---------------- attention ----------------
__global__ void k_att1(const int* __restrict__ batch) {
    int n = blockIdx.x * 8 + (threadIdx.x >> 5);
    int lane = threadIdx.x & 31;
    int b = batch[n];
    float v = g_out[n * D + lane] * g_hh[b * D + lane] +
              g_out[n * D + lane + 32] * g_hh[b * D + lane + 32];
#pragma unroll
    for (int off = 16; off; off >>= 1) v += __shfl_xor_sync(0xffffffffu, v, off);
    if (lane == 0) {
        g_e[n] = v;
        atomicMax(&g_segmax[b], fkey(v));
    }
}
__global__ void k_att2(const int* __restrict__ batch) {
    int n = blockIdx.x * 256 + threadIdx.x;
    if (n < NN) {
        int b = batch[n];
        float a = expf(g_e[n] - fdec(g_segmax[b]));
        g_a[n] = a;
        atomicAdd(&g_denom[b], a);
    }
}
__global__ void k_att3(const int* __restrict__ batch) {
    int g = threadIdx.x >> 6, o = threadIdx.x & 63;
    int n = blockIdx.x * 4 + g;
    int b = batch[n];
    float coeff = g_a[n] / (g_denom[b] + 1e-16f);
    atomicAdd(&g_r[b * D + o], coeff * g_out[n * D + o]);
}
__global__ void k_qstar() {
    int idx = blockIdx.x * 256 + threadIdx.x;
    int b = idx >> 7, t = idx & 127;
    g_qstar[idx] = (t < 64) ? g_hh[b * 64 + t] : g_r[b * 64 + t - 64];
}

// ---------------- output MLP ----------------
__global__ void k_final(const float* __restrict__ l1w, const float* __restrict__ l1b,
                        const float* __restrict__ l2w, const float* __restrict__ l2b,
                        float* __restrict__ y) {
    __shared__ float qs[128];
    __shared__ float y1[64];
    int b = blockIdx.x, tid = threadIdx.x;
    qs[tid] = g_qstar[b * 128 + tid];
    __syncthreads();
    if (tid < 64) {
        float acc = l1b[tid];
        const float* wr = l1w + tid * 128;
#pragma unroll 16
        for (int i = 0; i < 128; i++) acc += qs[i] * wr[i];
        y1[tid] = fmaxf(acc, 0.f) * l2w[tid];
    }
    __syncthreads();
    if (tid < 32) {
        float v = y1[tid] + y1[tid + 32];
#pragma unroll
        for (int off = 16; off; off >>= 1) v += __shfl_xor_sync(0xffffffffu, v, off);
        if (tid == 0) y[b] = v + l2b[0];
    }
}

// ---------------- launcher ----------------
extern "C" void kernel_launch(void* const* d_in, const int* in_sizes, int n_in,
                              void* d_out, int out_size) {
    const float* x        = (const float*)d_in[0];
    const int*   ei       = (const int*)d_in[1];
    const float* ea       = (const float*)d_in[2];
    const int*   batch    = (const int*)d_in[3];
    const float* lin0_w   = (const float*)d_in[4];
    const float* lin0_b   = (const float*)d_in[5];
    const float* nn_w1    = (const float*)d_in[6];
    const float* nn_b1    = (const float*)d_in[7];
    const float* nn_w2    = (const float*)d_in[8];
    const float* nn_b2    = (const float*)d_in[9];
    const float* conv_root= (const float*)d_in[10];
    const float* conv_bias= (const float*)d_in[11];
    const float* gwih     = (const float*)d_in[12];
    const float* gwhh     = (const float*)d_in[13];
    const float* gbih     = (const float*)d_in[14];
    const float* gbhh     = (const float*)d_in[15];
    const float* swih     = (const float*)d_in[16];
    const float* swhh     = (const float*)d_in[17];
    const float* sbih     = (const float*)d_in[18];
    const float* sbhh     = (const float*)d_in[19];
    const float* l1w      = (const float*)d_in[20];
    const float* l1b      = (const float*)d_in[21];
    const float* l2w      = (const float*)d_in[22];
    const float* l2b      = (const float*)d_in[23];
    float* yout = (float*)d_out;

    const int SMEM_GEMM  = 4 * 128 * LDW * 4;                                // 139264
    const int SMEM_NODE  = (4096 + 2 * 192 * 65 + 64 + 192 + 192 + 512) * 4; // 120064
    const int SMEM_LSTM  = (256 * 129 + 256 * 65 + 128 + 64 + 256) * 4;      // 200448
    cudaFuncSetAttribute(k_gemm_hmma, cudaFuncAttributeMaxDynamicSharedMemorySize, SMEM_GEMM);
    cudaFuncSetAttribute(k_node,  cudaFuncAttributeMaxDynamicSharedMemorySize, SMEM_NODE);
    cudaFuncSetAttribute(k_lstm,  cudaFuncAttributeMaxDynamicSharedMemorySize, SMEM_LSTM);

    // 1) node embedding
    k_lin0<<<NN / 4, 256>>>(x, lin0_w, lin0_b);
    // 2) degrees
    k_zero_invdeg<<<(NN + 255) / 256, 256>>>();
    k_deg<<<(NE + 255) / 256, 256>>>(ei);
    k_deg_fin<<<(NN + 255) / 256, 256>>>();
    // 3) edge network
    k_edge1<<<NE / 2, 256>>>(ea, nn_w1, nn_b1);
    k_w2conv<<<4096 * 128 / 256, 256>>>(nn_w2);
    k_gemm_hmma<<<dim3(32, (NE + 127) / 128), 256, SMEM_GEMM>>>(nn_b2);
    // 4) 3 rounds of message passing + GRU
    for (int t = 0; t < 3; t++) {
        k_zero_agg<<<NN * D / 256, 256>>>();
        k_msg<<<NE / 4, 256>>>(ei);
        k_node<<<592, 256, SMEM_NODE>>>(conv_root, conv_bias, gwih, gwhh, gbih, gbhh);
    }
    // 5) Set2Set
    k_zero_s2s<<<NB, 256>>>();
    for (int s = 0; s < 3; s++) {
        k_lstm<<<256, 256, SMEM_LSTM>>>(swih, swhh, sbih, sbhh);
        k_zero_att<<<(NB * 66 + 255) / 256, 256>>>();
        k_att1<<<NN / 8, 256>>>(batch);
        k_att2<<<(NN + 255) / 256, 256>>>(batch);
        k_att3<<<NN / 4, 256>>>(batch);
        k_qstar<<<NB * 128 / 256, 256>>>();
    }
    // 6) readout MLP
    k_final<<<NB, 128>>>(l1w, l1b, l2w, l2b, yout);
}

// round 4
// speedup vs baseline: 1.4457x; 1.1030x over previous
#include <cuda_runtime.h>
#include <cuda_bf16.h>
#include <cuda_fp16.h>
#include <math.h>
#include <stdint.h>

#define NN 50000
#define NE 100000
#define NB 2048
#define D  64

// ---------------- scratch (device globals; no allocation allowed) -------------
__device__ __align__(16) __nv_bfloat16 g_h1_hi[(size_t)NE * 128];
__device__ __align__(16) __nv_bfloat16 g_h1_lo[(size_t)NE * 128];
__device__ __align__(16) __nv_bfloat16 g_w2_hi[(size_t)4096 * 128];
__device__ __align__(16) __nv_bfloat16 g_w2_lo[(size_t)4096 * 128];
__device__ __align__(16) __half g_ew[(size_t)NE * 4096];   // 0.82 GB fp16
__device__ float    g_out[NN * D];              // node state (h == out)
__device__ float    g_agg[NN * D];              // message accumulator
__device__ float    g_invdeg[NN];
__device__ float    g_e[NN];
__device__ float    g_a[NN];
__device__ unsigned g_segmax[NB];
__device__ float    g_denom[NB];
__device__ float    g_r[NB * D];
__device__ float    g_qstar[NB * 2 * D];
__device__ float    g_hh[NB * D];
__device__ float    g_cc[NB * D];

__device__ __forceinline__ float sigmoidf_(float x) { return 1.f / (1.f + expf(-x)); }

__device__ __forceinline__ unsigned fkey(float f) {
    unsigned b = __float_as_uint(f);
    return (b & 0x80000000u) ? ~b : (b | 0x80000000u);
}
__device__ __forceinline__ float fdec(unsigned k) {
    unsigned b = (k & 0x80000000u) ? (k ^ 0x80000000u) : ~k;
    return __uint_as_float(b);
}

// ---------------- zero kernels ----------------
__global__ void k_zero_invdeg() {
    int i = blockIdx.x * 256 + threadIdx.x;
    if (i < NN) g_invdeg[i] = 0.f;
}
__global__ void k_zero_agg() {
    int i = blockIdx.x * 256 + threadIdx.x;
    g_agg[i] = 0.f;
}
__global__ void k_zero_s2s() {
    int i = blockIdx.x * 256 + threadIdx.x;
    if (i < NB * 128) g_qstar[i] = 0.f;
    else if (i < NB * 192) g_hh[i - NB * 128] = 0.f;
    else g_cc[i - NB * 192] = 0.f;
}
__global__ void k_zero_att() {
    int i = blockIdx.x * 256 + threadIdx.x;
    if (i < NB) { g_denom[i] = 0.f; g_segmax[i] = 0u; }
    else if (i < NB + NB * 64) g_r[i - NB] = 0.f;
}

// ---------------- lin0 + relu ----------------
__global__ void k_lin0(const float* __restrict__ x, const float* __restrict__ w,
                       const float* __restrict__ b) {
    __shared__ float xs[4][14];
    int g = threadIdx.x >> 6, o = threadIdx.x & 63;
    int n = blockIdx.x * 4 + g;
    if (o < 14) xs[g][o] = x[n * 14 + o];
    __syncthreads();
    float acc = b[o];
#pragma unroll
    for (int j = 0; j < 14; j++) acc += xs[g][j] * w[o * 14 + j];
    g_out[n * D + o] = fmaxf(acc, 0.f);
}

// ---------------- degree ----------------
__global__ void k_deg(const int* __restrict__ ei) {
    int e = blockIdx.x * 256 + threadIdx.x;
    if (e < NE) atomicAdd(&g_invdeg[ei[NE + e]], 1.f);
}
__global__ void k_deg_fin() {
    int n = blockIdx.x * 256 + threadIdx.x;
    if (n < NN) g_invdeg[n] = 1.f / fmaxf(g_invdeg[n], 1.f);
}

// ---------------- edge net layer 1 (writes split bf16) ----------------
__global__ void k_edge1(const float* __restrict__ ea, const float* __restrict__ w1,
                        const float* __restrict__ b1) {
    int k = threadIdx.x & 127;
    int e = blockIdx.x * 2 + (threadIdx.x >> 7);
    float a0 = ea[e * 4 + 0], a1 = ea[e * 4 + 1], a2 = ea[e * 4 + 2], a3 = ea[e * 4 + 3];
    float acc = b1[k] + a0 * w1[k * 4 + 0] + a1 * w1[k * 4 + 1] +
                a2 * w1[k * 4 + 2] + a3 * w1[k * 4 + 3];
    acc = fmaxf(acc, 0.f);
    __nv_bfloat16 hi = __float2bfloat16(acc);
    size_t idx = (size_t)e * 128 + k;
    g_h1_hi[idx] = hi;
    g_h1_lo[idx] = __float2bfloat16(acc - __bfloat162float(hi));
}

// ---------------- W2 fp32 -> bf16 hi/lo split ----------------
__global__ void k_w2conv(const float* __restrict__ w2) {
    int i = blockIdx.x * 256 + threadIdx.x;  // covers 4096*128
    float v = w2[i];
    __nv_bfloat16 hi = __float2bfloat16(v);
    g_w2_hi[i] = hi;
    g_w2_lo[i] = __float2bfloat16(v - __bfloat162float(hi));
}

// ---------------- HMMA helper ----------------
__device__ __forceinline__ void mma_bf16(float* c, const uint32_t* a,
                                         uint32_t b0, uint32_t b1) {
    asm volatile(
        "mma.sync.aligned.m16n8k16.row.col.f32.bf16.bf16.f32 "
        "{%0,%1,%2,%3}, {%4,%5,%6,%7}, {%8,%9}, {%0,%1,%2,%3};"
        : "+f"(c[0]), "+f"(c[1]), "+f"(c[2]), "+f"(c[3])
        : "r"(a[0]), "r"(a[1]), "r"(a[2]), "r"(a[3]), "r"(b0), "r"(b1));
}

// ---------------- big GEMM on HMMA: ew = h1 @ W2^T + b2 (fp16 out) ----------
// M=1e5 (pad 128), N=4096, K=128. Split-bf16 x3 passes, fp32 accum.
// SMEM word layout: [row][68 words], word = 2 bf16 (k-contiguous).
#define LDW 68
__global__ void __launch_bounds__(256, 1)
k_gemm_hmma(const float* __restrict__ b2) {
    extern __shared__ uint32_t sw[];
    uint32_t* A_HI = sw;
    uint32_t* A_LO = A_HI + 128 * LDW;
    uint32_t* B_HI = A_LO + 128 * LDW;
    uint32_t* B_LO = B_HI + 128 * LDW;
    const int tid = threadIdx.x;
    const int m0 = blockIdx.y * 128, n0 = blockIdx.x * 128;

    // ---- load tiles: threads 0-127 -> A row tid; 128-255 -> B row tid-128
    {
        int r = tid & 127;
        bool isA = tid < 128;
        const uint4 *sh, *sl;
        uint32_t *dh, *dl;
        bool valid = true;
        if (isA) {
            int m = m0 + r;
            valid = m < NE;
            sh = (const uint4*)(g_h1_hi + (size_t)m * 128);
            sl = (const uint4*)(g_h1_lo + (size_t)m * 128);
            dh = A_HI + r * LDW; dl = A_LO + r * LDW;
        } else {
            int n = n0 + r;
            sh = (const uint4*)(g_w2_hi + (size_t)n * 128);
            sl = (const uint4*)(g_w2_lo + (size_t)n * 128);
            dh = B_HI + r * LDW; dl = B_LO + r * LDW;
        }
#pragma unroll
        for (int kc = 0; kc < 16; kc++) {
            uint4 vh = valid ? sh[kc] : make_uint4(0u, 0u, 0u, 0u);
            uint4 vl = valid ? sl[kc] : make_uint4(0u, 0u, 0u, 0u);
            *(uint4*)(dh + kc * 4) = vh;
            *(uint4*)(dl + kc * 4) = vl;
        }
    }
    __syncthreads();

    const int wid = tid >> 5, lane = tid & 31;
    const int warpM = wid >> 1, warpN = wid & 1;
    const int g = lane >> 2, tg = lane & 3;

    float c[2][8][4];
#pragma unroll
    for (int mi = 0; mi < 2; mi++)
#pragma unroll
        for (int ni = 0; ni < 8; ni++)
#pragma unroll
            for (int q = 0; q < 4; q++) c[mi][ni][q] = 0.f;

    const uint32_t* Apass[3] = {A_HI, A_HI, A_LO};
    const uint32_t* Bpass[3] = {B_HI, B_LO, B_HI};

#pragma unroll
    for (int p = 0; p < 3; p++) {
        const uint32_t* As = Apass[p];
        const uint32_t* Bs = Bpass[p];
#pragma unroll
        for (int s = 0; s < 8; s++) {
            const int kw = s * 8 + tg;
            uint32_t a[2][4];
#pragma unroll
            for (int mi = 0; mi < 2; mi++) {
                const uint32_t* ar = As + (warpM * 32 + mi * 16 + g) * LDW;
                a[mi][0] = ar[kw];
                a[mi][1] = ar[8 * LDW + kw];
                a[mi][2] = ar[kw + 4];
                a[mi][3] = ar[8 * LDW + kw + 4];
            }
#pragma unroll
            for (int ni = 0; ni < 8; ni++) {
                const uint32_t* br = Bs + (warpN * 64 + ni * 8 + g) * LDW;
                uint32_t b0 = br[kw], b1 = br[kw + 4];
                mma_bf16(c[0][ni], a[0], b0, b1);
                mma_bf16(c[1][ni], a[1], b0, b1);
            }
        }
    }

    // ---- epilogue: bias + convert to fp16 + store
    {
        const int colbase = n0 + warpN * 64 + 2 * tg;
        float2 bias[8];
#pragma unroll
        for (int ni = 0; ni < 8; ni++)
            bias[ni] = *(const float2*)(b2 + colbase + ni * 8);
#pragma unroll
        for (int mi = 0; mi < 2; mi++) {
            int r0 = m0 + warpM * 32 + mi * 16 + g;
            if (r0 < NE) {
                __half2* rp = (__half2*)(g_ew + (size_t)r0 * 4096 + colbase);
#pragma unroll
                for (int ni = 0; ni < 8; ni++)
                    rp[ni * 4] = __floats2half2_rn(c[mi][ni][0] + bias[ni].x,
                                                   c[mi][ni][1] + bias[ni].y);
            }
            int r1 = r0 + 8;
            if (r1 < NE) {
                __half2* rp = (__half2*)(g_ew + (size_t)r1 * 4096 + colbase);
#pragma unroll
                for (int ni = 0; ni < 8; ni++)
                    rp[ni * 4] = __floats2half2_rn(c[mi][ni][2] + bias[ni].x,
                                                   c[mi][ni][3] + bias[ni].y);
            }
        }
    }
}

// ---------------- per-edge matvec + scatter (one warp per edge) -------------
__global__ void k_msg(const int* __restrict__ ei) {
    __shared__ float so[8][64];
    int g = threadIdx.x >> 5, o2 = threadIdx.x & 31;
    int e = blockIdx.x * 8 + g;
    int s = ei[e], d = ei[NE + e];
    *(float2*)&so[g][o2 * 2] = *(const float2*)(g_out + s * D + o2 * 2);
    __syncwarp();
    const __half2* ewp = (const __half2*)g_ew + (size_t)e * 2048 + o2;
    float ax = 0.f, ay = 0.f;
#pragma unroll 16
    for (int i = 0; i < 64; i++) {
        float2 w = __half22float2(__ldg(ewp + i * 32));
        float sv = so[g][i];
        ax += sv * w.x;
        ay += sv * w.y;
    }
    atomicAdd(&g_agg[d * D + 2 * o2], ax);
    atomicAdd(&g_agg[d * D + 2 * o2 + 1], ay);
}

// ---------------- fused conv_root + GRU ----------------
__global__ void k_node(const float* __restrict__ root, const float* __restrict__ cbias,
                       const float* __restrict__ wih, const float* __restrict__ whh,
                       const float* __restrict__ bih, const float* __restrict__ bhh) {
    extern __shared__ float sm[];
    float* root_s = sm;                 // 4096
    float* wih_s  = sm + 4096;          // 192*65
    float* whh_s  = wih_s + 192 * 65;
    float* cb_s   = whh_s + 192 * 65;   // 64
    float* bih_s  = cb_s + 64;          // 192
    float* bhh_s  = bih_s + 192;        // 192
    float* orow   = bhh_s + 192;        // 4*64
    float* mrow   = orow + 256;         // 4*64
    int tid = threadIdx.x;
    for (int i = tid; i < 4096; i += 256) root_s[i] = root[i];
    for (int i = tid; i < 192 * 64; i += 256) {
        int rr = i >> 6, cc = i & 63;
        wih_s[rr * 65 + cc] = wih[i];
        whh_s[rr * 65 + cc] = whh[i];
    }
    if (tid < 64) cb_s[tid] = cbias[tid];
    if (tid < 192) { bih_s[tid] = bih[tid]; bhh_s[tid] = bhh[tid]; }
    __syncthreads();
    int g = tid >> 6, o = tid & 63;
    for (int base = blockIdx.x * 4; base < NN; base += gridDim.x * 4) {
        int n = base + g;
        bool valid = n < NN;
        float h = valid ? g_out[n * D + o] : 0.f;
        orow[g * 64 + o] = h;
        __syncthreads();
        float m = cb_s[o];
        if (valid) m += g_agg[n * D + o] * g_invdeg[n];
#pragma unroll 16
        for (int i = 0; i < 64; i++) m += orow[g * 64 + i] * root_s[i * 64 + o];
        m = fmaxf(m, 0.f);
        mrow[g * 64 + o] = m;
        __syncthreads();
        float gi0 = bih_s[o], gi1 = bih_s[64 + o], gi2 = bih_s[128 + o];
        float gh0 = bhh_s[o], gh1 = bhh_s[64 + o], gh2 = bhh_s[128 + o];
        const float* w0 = wih_s + o * 65;
        const float* w1 = wih_s + (64 + o) * 65;
        const float* w2 = wih_s + (128 + o) * 65;
        const float* v0 = whh_s + o * 65;
        const float* v1 = whh_s + (64 + o) * 65;
        const float* v2 = whh_s + (128 + o) * 65;
#pragma unroll 8
        for (int i = 0; i < 64; i++) {
            float mi = mrow[g * 64 + i], hi = orow[g * 64 + i];
            gi0 += mi * w0[i]; gi1 += mi * w1[i]; gi2 += mi * w2[i];
            gh0 += hi * v0[i]; gh1 += hi * v1[i]; gh2 += hi * v2[i];
        }
        float r  = sigmoidf_(gi0 + gh0);
        float z  = sigmoidf_(gi1 + gh1);
        float nn = tanhf(gi2 + r * gh2);
        float hn = (1.f - z) * nn + z * h;
        __syncthreads();
        if (valid) g_out[n * D + o] = hn;
    }
}

// ---------------- Set2Set LSTM cell ----------------
__global__ void k_lstm(const float* __restrict__ wih, const float* __restrict__ whh,
                       const float* __restrict__ bih, const float* __restrict__ bhh) {
    extern __shared__ float sm[];
    float* wih_s = sm;                   // 256*129
    float* whh_s = wih_s + 256 * 129;    // 256*65
    float* qs    = whh_s + 256 * 65;     // 128
    float* hs    = qs + 128;             // 64
    float* gsh   = hs + 64;              // 256
    int tid = threadIdx.x;
    for (int i = tid; i < 256 * 128; i += 256) {
        int rr = i >> 7, cc = i & 127;
        wih_s[rr * 129 + cc] = wih[i];
    }
    for (int i = tid; i < 256 * 64; i += 256) {
        int rr = i >> 6, cc = i & 63;
        whh_s[rr * 65 + cc] = whh[i];
    }
    float bsum = bih[tid] + bhh[tid];
    __syncthreads();
    for (int it = 0; it < 8; it++) {
        int b = blockIdx.x + 256 * it;
        if (tid < 128) qs[tid] = g_qstar[b * 128 + tid];
        if (tid < 64)  hs[tid] = g_hh[b * 64 + tid];
        __syncthreads();
        float acc = bsum;
        const float* wr = wih_s + tid * 129;
#pragma unroll 16
        for (int i = 0; i < 128; i++) acc += qs[i] * wr[i];
        const float* vr = whh_s + tid * 65;
#pragma unroll 16
        for (int i = 0; i < 64; i++) acc += hs[i] * vr[i];
        gsh[tid] = acc;
        __syncthreads();
        if (tid < 64) {
            float ii = gsh[tid], ff = gsh[64 + tid], gg = gsh[128 + tid], oo = gsh[192 + tid];
            float c  = sigmoidf_(ff) * g_cc[b * 64 + tid] + sigmoidf_(ii) * tanhf(gg);
            float h2 = sigmoidf_(oo) * tanhf(c);
            g_cc[b * 64 + tid] = c;
            g_hh[b * 64 + tid] = h2;
        }
        __syncthreads();
    }
}

// ---------------- attention ----------------
__global__ void k_att1(const int* __restrict__ batch) {
    int n = blockIdx.x * 8 + (threadIdx.x >> 5);
    int lane = threadIdx.x & 31;
    int b = batch[n];
    float v = g_out[n * D + lane] * g_hh[b * D + lane] +
              g_out[n * D + lane + 32] * g_hh[b * D + lane + 32];
#pragma unroll
    for (int off = 16; off; off >>= 1) v += __shfl_xor_sync(0xffffffffu, v, off);
    if (lane == 0) {
        g_e[n] = v;
        atomicMax(&g_segmax[b], fkey(v));
    }
}
__global__ void k_att2(const int* __restrict__ batch) {
    int n = blockIdx.x * 256 + threadIdx.x;
    if (n < NN) {
        int b = batch[n];
        float a = expf(g_e[n] - fdec(g_segmax[b]));
        g_a[n] = a;
        atomicAdd(&g_denom[b], a);
    }
}
__global__ void k_att3(const int* __restrict__ batch) {
    int g = threadIdx.x >> 6, o = threadIdx.x & 63;
    int n = blockIdx.x * 4 + g;
    int b = batch[n];
    float coeff = g_a[n] / (g_denom[b] + 1e-16f);
    atomicAdd(&g_r[b * D + o], coeff * g_out[n * D + o]);
}
__global__ void k_qstar() {
    int idx = blockIdx.x * 256 + threadIdx.x;
    int b = idx >> 7, t = idx & 127;
    g_qstar[idx] = (t < 64) ? g_hh[b * 64 + t] : g_r[b * 64 + t - 64];
}

// ---------------- output MLP ----------------
__global__ void k_final(const float* __restrict__ l1w, const float* __restrict__ l1b,
                        const float* __restrict__ l2w, const float* __restrict__ l2b,
                        float* __restrict__ y) {
    __shared__ float qs[128];
    __shared__ float y1[64];
    int b = blockIdx.x, tid = threadIdx.x;
    qs[tid] = g_qstar[b * 128 + tid];
    __syncthreads();
    if (tid < 64) {
        float acc = l1b[tid];
        const float* wr = l1w + tid * 128;
#pragma unroll 16
        for (int i = 0; i < 128; i++) acc += qs[i] * wr[i];
        y1[tid] = fmaxf(acc, 0.f) * l2w[tid];
    }
    __syncthreads();
    if (tid < 32) {
        float v = y1[tid] + y1[tid + 32];
#pragma unroll
        for (int off = 16; off; off >>= 1) v += __shfl_xor_sync(0xffffffffu, v, off);
        if (tid == 0) y[b] = v + l2b[0];
    }
}

// ---------------- launcher ----------------
extern "C" void kernel_launch(void* const* d_in, const int* in_sizes, int n_in,
                              void* d_out, int out_size) {
    const float* x        = (const float*)d_in[0];
    const int*   ei       = (const int*)d_in[1];
    const float* ea       = (const float*)d_in[2];
    const int*   batch    = (const int*)d_in[3];
    const float* lin0_w   = (const float*)d_in[4];
    const float* lin0_b   = (const float*)d_in[5];
    const float* nn_w1    = (const float*)d_in[6];
    const float* nn_b1    = (const float*)d_in[7];
    const float* nn_w2    = (const float*)d_in[8];
    const float* nn_b2    = (const float*)d_in[9];
    const float* conv_root= (const float*)d_in[10];
    const float* conv_bias= (const float*)d_in[11];
    const float* gwih     = (const float*)d_in[12];
    const float* gwhh     = (const float*)d_in[13];
    const float* gbih     = (const float*)d_in[14];
    const float* gbhh     = (const float*)d_in[15];
    const float* swih     = (const float*)d_in[16];
    const float* swhh     = (const float*)d_in[17];
    const float* sbih     = (const float*)d_in[18];
    const float* sbhh     = (const float*)d_in[19];
    const float* l1w      = (const float*)d_in[20];
    const float* l1b      = (const float*)d_in[21];
    const float* l2w      = (const float*)d_in[22];
    const float* l2b      = (const float*)d_in[23];
    float* yout = (float*)d_out;

    const int SMEM_GEMM  = 4 * 128 * LDW * 4;                                // 139264
    const int SMEM_NODE  = (4096 + 2 * 192 * 65 + 64 + 192 + 192 + 512) * 4; // 120064
    const int SMEM_LSTM  = (256 * 129 + 256 * 65 + 128 + 64 + 256) * 4;      // 200448
    cudaFuncSetAttribute(k_gemm_hmma, cudaFuncAttributeMaxDynamicSharedMemorySize, SMEM_GEMM);
    cudaFuncSetAttribute(k_node,  cudaFuncAttributeMaxDynamicSharedMemorySize, SMEM_NODE);
    cudaFuncSetAttribute(k_lstm,  cudaFuncAttributeMaxDynamicSharedMemorySize, SMEM_LSTM);

    // 1) node embedding
    k_lin0<<<NN / 4, 256>>>(x, lin0_w, lin0_b);
    // 2) degrees
    k_zero_invdeg<<<(NN + 255) / 256, 256>>>();
    k_deg<<<(NE + 255) / 256, 256>>>(ei);
    k_deg_fin<<<(NN + 255) / 256, 256>>>();
    // 3) edge network
    k_edge1<<<NE / 2, 256>>>(ea, nn_w1, nn_b1);
    k_w2conv<<<4096 * 128 / 256, 256>>>(nn_w2);
    k_gemm_hmma<<<dim3(32, (NE + 127) / 128), 256, SMEM_GEMM>>>(nn_b2);
    // 4) 3 rounds of message passing + GRU
    for (int t = 0; t < 3; t++) {
        k_zero_agg<<<NN * D / 256, 256>>>();
        k_msg<<<NE / 8, 256>>>(ei);
        k_node<<<592, 256, SMEM_NODE>>>(conv_root, conv_bias, gwih, gwhh, gbih, gbhh);
    }
    // 5) Set2Set
    k_zero_s2s<<<NB, 256>>>();
    for (int s = 0; s < 3; s++) {
        k_lstm<<<256, 256, SMEM_LSTM>>>(swih, swhh, sbih, sbhh);
        k_zero_att<<<(NB * 66 + 255) / 256, 256>>>();
        k_att1<<<NN / 8, 256>>>(batch);
        k_att2<<<(NN + 255) / 256, 256>>>(batch);
        k_att3<<<NN / 4, 256>>>(batch);
        k_qstar<<<NB * 128 / 256, 256>>>();
    }
    // 6) readout MLP
    k_final<<<NB, 128>>>(l1w, l1b, l2w, l2b, yout);
}

// round 5
// speedup vs baseline: 1.9425x; 1.3437x over previous
#include <cuda_runtime.h>
#include <cuda_bf16.h>
#include <cuda_fp16.h>
#include <math.h>
#include <stdint.h>

#define NN 50000
#define NE 100000
#define NB 2048
#define D  64

// ---------------- scratch (device globals; no allocation allowed) -------------
__device__ __align__(16) __nv_bfloat16 g_h1b[(size_t)NE * 128];
__device__ __align__(16) __nv_bfloat16 g_w2b[(size_t)4096 * 128];
__device__ __align__(16) __half g_ew[(size_t)NE * 4096];   // 0.82 GB fp16
__device__ float    g_out[NN * D];              // node state (h == out)
__device__ float    g_agg[NN * D];              // message accumulator
__device__ float    g_invdeg[NN];
__device__ float    g_e[NN];
__device__ float    g_a[NN];
__device__ unsigned g_segmax[NB];
__device__ float    g_denom[NB];
__device__ float    g_r[NB * D];
__device__ float    g_qstar[NB * 2 * D];
__device__ float    g_hh[NB * D];
__device__ float    g_cc[NB * D];

__device__ __forceinline__ float sigmoidf_(float x) { return 1.f / (1.f + expf(-x)); }

__device__ __forceinline__ unsigned fkey(float f) {
    unsigned b = __float_as_uint(f);
    return (b & 0x80000000u) ? ~b : (b | 0x80000000u);
}
__device__ __forceinline__ float fdec(unsigned k) {
    unsigned b = (k & 0x80000000u) ? (k ^ 0x80000000u) : ~k;
    return __uint_as_float(b);
}

// ---------------- zero kernels ----------------
__global__ void k_zero_invdeg() {
    int i = blockIdx.x * 256 + threadIdx.x;
    if (i < NN) g_invdeg[i] = 0.f;
}
__global__ void k_zero_agg() {
    int i = blockIdx.x * 256 + threadIdx.x;
    g_agg[i] = 0.f;
}
__global__ void k_zero_s2s() {
    int i = blockIdx.x * 256 + threadIdx.x;
    if (i < NB * 128) g_qstar[i] = 0.f;
    else if (i < NB * 192) g_hh[i - NB * 128] = 0.f;
    else g_cc[i - NB * 192] = 0.f;
}
__global__ void k_zero_att() {
    int i = blockIdx.x * 256 + threadIdx.x;
    if (i < NB) { g_denom[i] = 0.f; g_segmax[i] = 0u; }
    else if (i < NB + NB * 64) g_r[i - NB] = 0.f;
}

// ---------------- lin0 + relu ----------------
__global__ void k_lin0(const float* __restrict__ x, const float* __restrict__ w,
                       const float* __restrict__ b) {
    __shared__ float xs[4][14];
    int g = threadIdx.x >> 6, o = threadIdx.x & 63;
    int n = blockIdx.x * 4 + g;
    if (o < 14) xs[g][o] = x[n * 14 + o];
    __syncthreads();
    float acc = b[o];
#pragma unroll
    for (int j = 0; j < 14; j++) acc += xs[g][j] * w[o * 14 + j];
    g_out[n * D + o] = fmaxf(acc, 0.f);
}

// ---------------- degree ----------------
__global__ void k_deg(const int* __restrict__ ei) {
    int e = blockIdx.x * 256 + threadIdx.x;
    if (e < NE) atomicAdd(&g_invdeg[ei[NE + e]], 1.f);
}
__global__ void k_deg_fin() {
    int n = blockIdx.x * 256 + threadIdx.x;
    if (n < NN) g_invdeg[n] = 1.f / fmaxf(g_invdeg[n], 1.f);
}

// ---------------- edge net layer 1 (bf16 out) ----------------
__global__ void k_edge1(const float* __restrict__ ea, const float* __restrict__ w1,
                        const float* __restrict__ b1) {
    int k = threadIdx.x & 127;
    int e = blockIdx.x * 2 + (threadIdx.x >> 7);
    float a0 = ea[e * 4 + 0], a1 = ea[e * 4 + 1], a2 = ea[e * 4 + 2], a3 = ea[e * 4 + 3];
    float acc = b1[k] + a0 * w1[k * 4 + 0] + a1 * w1[k * 4 + 1] +
                a2 * w1[k * 4 + 2] + a3 * w1[k * 4 + 3];
    g_h1b[(size_t)e * 128 + k] = __float2bfloat16(fmaxf(acc, 0.f));
}

// ---------------- W2 fp32 -> bf16 ----------------
__global__ void k_w2conv(const float* __restrict__ w2) {
    int i = blockIdx.x * 256 + threadIdx.x;  // covers 4096*128
    g_w2b[i] = __float2bfloat16(w2[i]);
}

// ---------------- HMMA helper ----------------
__device__ __forceinline__ void mma_bf16(float* c, const uint32_t* a,
                                         uint32_t b0, uint32_t b1) {
    asm volatile(
        "mma.sync.aligned.m16n8k16.row.col.f32.bf16.bf16.f32 "
        "{%0,%1,%2,%3}, {%4,%5,%6,%7}, {%8,%9}, {%0,%1,%2,%3};"
        : "+f"(c[0]), "+f"(c[1]), "+f"(c[2]), "+f"(c[3])
        : "r"(a[0]), "r"(a[1]), "r"(a[2]), "r"(a[3]), "r"(b0), "r"(b1));
}

// ---------------- big GEMM on HMMA: ew = h1 @ W2^T + b2 (fp16 out) ----------
// M=1e5 (pad 128), N=4096, K=128. Single-pass bf16, fp32 accum.
// SMEM word layout: [row][68 words], word = 2 bf16 (k-contiguous).
#define LDW 68
__global__ void __launch_bounds__(256, 2)
k_gemm_hmma(const float* __restrict__ b2) {
    extern __shared__ uint32_t sw[];
    uint32_t* As = sw;                 // 128*LDW
    uint32_t* Bs = As + 128 * LDW;     // 128*LDW
    const int tid = threadIdx.x;
    const int m0 = blockIdx.y * 128, n0 = blockIdx.x * 128;

    // ---- load tiles: threads 0-127 -> A row tid; 128-255 -> B row tid-128
    {
        int r = tid & 127;
        bool isA = tid < 128;
        const uint4* src;
        uint32_t* dst;
        bool valid = true;
        if (isA) {
            int m = m0 + r;
            valid = m < NE;
            src = (const uint4*)(g_h1b + (size_t)m * 128);
            dst = As + r * LDW;
        } else {
            int n = n0 + r;
            src = (const uint4*)(g_w2b + (size_t)n * 128);
            dst = Bs + r * LDW;
        }
#pragma unroll
        for (int kc = 0; kc < 16; kc++) {
            uint4 v = valid ? src[kc] : make_uint4(0u, 0u, 0u, 0u);
            *(uint4*)(dst + kc * 4) = v;
        }
    }
    __syncthreads();

    const int wid = tid >> 5, lane = tid & 31;
    const int warpM = wid >> 1, warpN = wid & 1;
    const int g = lane >> 2, tg = lane & 3;

    float c[2][8][4];
#pragma unroll
    for (int mi = 0; mi < 2; mi++)
#pragma unroll
        for (int ni = 0; ni < 8; ni++)
#pragma unroll
            for (int q = 0; q < 4; q++) c[mi][ni][q] = 0.f;

#pragma unroll
    for (int s = 0; s < 8; s++) {
        const int kw = s * 8 + tg;
        uint32_t a[2][4];
#pragma unroll
        for (int mi = 0; mi < 2; mi++) {
            const uint32_t* ar = As + (warpM * 32 + mi * 16 + g) * LDW;
            a[mi][0] = ar[kw];
            a[mi][1] = ar[8 * LDW + kw];
            a[mi][2] = ar[kw + 4];
            a[mi][3] = ar[8 * LDW + kw + 4];
        }
#pragma unroll
        for (int ni = 0; ni < 8; ni++) {
            const uint32_t* br = Bs + (warpN * 64 + ni * 8 + g) * LDW;
            uint32_t b0 = br[kw], b1 = br[kw + 4];
            mma_bf16(c[0][ni], a[0], b0, b1);
            mma_bf16(c[1][ni], a[1], b0, b1);
        }
    }

    // ---- epilogue: bias + convert to fp16 + store
    {
        const int colbase = n0 + warpN * 64 + 2 * tg;
        float2 bias[8];
#pragma unroll
        for (int ni = 0; ni < 8; ni++)
            bias[ni] = *(const float2*)(b2 + colbase + ni * 8);
#pragma unroll
        for (int mi = 0; mi < 2; mi++) {
            int r0 = m0 + warpM * 32 + mi * 16 + g;
            if (r0 < NE) {
                __half2* rp = (__half2*)(g_ew + (size_t)r0 * 4096 + colbase);
#pragma unroll
                for (int ni = 0; ni < 8; ni++)
                    rp[ni * 4] = __floats2half2_rn(c[mi][ni][0] + bias[ni].x,
                                                   c[mi][ni][1] + bias[ni].y);
            }
            int r1 = r0 + 8;
            if (r1 < NE) {
                __half2* rp = (__half2*)(g_ew + (size_t)r1 * 4096 + colbase);
#pragma unroll
                for (int ni = 0; ni < 8; ni++)
                    rp[ni * 4] = __floats2half2_rn(c[mi][ni][2] + bias[ni].x,
                                                   c[mi][ni][3] + bias[ni].y);
            }
        }
    }
}

// ---------------- per-edge matvec + scatter (one warp per edge) -------------
__global__ void k_msg(const int* __restrict__ ei) {
    __shared__ float so[8][64];
    int g = threadIdx.x >> 5, o2 = threadIdx.x & 31;
    int e = blockIdx.x * 8 + g;
    int s = ei[e], d = ei[NE + e];
    *(float2*)&so[g][o2 * 2] = *(const float2*)(g_out + s * D + o2 * 2);
    __syncwarp();
    const __half2* ewp = (const __half2*)g_ew + (size_t)e * 2048 + o2;
    float ax = 0.f, ay = 0.f;
#pragma unroll 16
    for (int i = 0; i < 64; i++) {
        float2 w = __half22float2(__ldg(ewp + i * 32));
        float sv = so[g][i];
        ax += sv * w.x;
        ay += sv * w.y;
    }
    atomicAdd(&g_agg[d * D + 2 * o2], ax);
    atomicAdd(&g_agg[d * D + 2 * o2 + 1], ay);
}

// ---------------- fused conv_root + GRU ----------------
__global__ void k_node(const float* __restrict__ root, const float* __restrict__ cbias,
                       const float* __restrict__ wih, const float* __restrict__ whh,
                       const float* __restrict__ bih, const float* __restrict__ bhh) {
    extern __shared__ float sm[];
    float* root_s = sm;                 // 4096
    float* wih_s  = sm + 4096;          // 192*65
    float* whh_s  = wih_s + 192 * 65;
    float* cb_s   = whh_s + 192 * 65;   // 64
    float* bih_s  = cb_s + 64;          // 192
    float* bhh_s  = bih_s + 192;        // 192
    float* orow   = bhh_s + 192;        // 4*64
    float* mrow   = orow + 256;         // 4*64
    int tid = threadIdx.x;
    for (int i = tid; i < 4096; i += 256) root_s[i] = root[i];
    for (int i = tid; i < 192 * 64; i += 256) {
        int rr = i >> 6, cc = i & 63;
        wih_s[rr * 65 + cc] = wih[i];
        whh_s[rr * 65 + cc] = whh[i];
    }
    if (tid < 64) cb_s[tid] = cbias[tid];
    if (tid < 192) { bih_s[tid] = bih[tid]; bhh_s[tid] = bhh[tid]; }
    __syncthreads();
    int g = tid >> 6, o = tid & 63;
    for (int base = blockIdx.x * 4; base < NN; base += gridDim.x * 4) {
        int n = base + g;
        bool valid = n < NN;
        float h = valid ? g_out[n * D + o] : 0.f;
        orow[g * 64 + o] = h;
        __syncthreads();
        float m = cb_s[o];
        if (valid) m += g_agg[n * D + o] * g_invdeg[n];
#pragma unroll 16
        for (int i = 0; i < 64; i++) m += orow[g * 64 + i] * root_s[i * 64 + o];
        m = fmaxf(m, 0.f);
        mrow[g * 64 + o] = m;
        __syncthreads();
        float gi0 = bih_s[o], gi1 = bih_s[64 + o], gi2 = bih_s[128 + o];
        float gh0 = bhh_s[o], gh1 = bhh_s[64 + o], gh2 = bhh_s[128 + o];
        const float* w0 = wih_s + o * 65;
        const float* w1 = wih_s + (64 + o) * 65;
        const float* w2 = wih_s + (128 + o) * 65;
        const float* v0 = whh_s + o * 65;
        const float* v1 = whh_s + (64 + o) * 65;
        const float* v2 = whh_s + (128 + o) * 65;
#pragma unroll 8
        for (int i = 0; i < 64; i++) {
            float mi = mrow[g * 64 + i], hi = orow[g * 64 + i];
            gi0 += mi * w0[i]; gi1 += mi * w1[i]; gi2 += mi * w2[i];
            gh0 += hi * v0[i]; gh1 += hi * v1[i]; gh2 += hi * v2[i];
        }
        float r  = sigmoidf_(gi0 + gh0);
        float z  = sigmoidf_(gi1 + gh1);
        float nn = tanhf(gi2 + r * gh2);
        float hn = (1.f - z) * nn + z * h;
        __syncthreads();
        if (valid) g_out[n * D + o] = hn;
    }
}

// ---------------- Set2Set LSTM cell ----------------
__global__ void k_lstm(const float* __restrict__ wih, const float* __restrict__ whh,
                       const float* __restrict__ bih, const float* __restrict__ bhh) {
    extern __shared__ float sm[];
    float* wih_s = sm;                   // 256*129
    float* whh_s = wih_s + 256 * 129;    // 256*65
    float* qs    = whh_s + 256 * 65;     // 128
    float* hs    = qs + 128;             // 64
    float* gsh   = hs + 64;              // 256
    int tid = threadIdx.x;
    for (int i = tid; i < 256 * 128; i += 256) {
        int rr = i >> 7, cc = i & 127;
        wih_s[rr * 129 + cc] = wih[i];
    }
    for (int i = tid; i < 256 * 64; i += 256) {
        int rr = i >> 6, cc = i & 63;
        whh_s[rr * 65 + cc] = whh[i];
    }
    float bsum = bih[tid] + bhh[tid];
    __syncthreads();
    for (int it = 0; it < 8; it++) {
        int b = blockIdx.x + 256 * it;
        if (tid < 128) qs[tid] = g_qstar[b * 128 + tid];
        if (tid < 64)  hs[tid] = g_hh[b * 64 + tid];
        __syncthreads();
        float acc = bsum;
        const float* wr = wih_s + tid * 129;
#pragma unroll 16
        for (int i = 0; i < 128; i++) acc += qs[i] * wr[i];
        const float* vr = whh_s + tid * 65;
#pragma unroll 16
        for (int i = 0; i < 64; i++) acc += hs[i] * vr[i];
        gsh[tid] = acc;
        __syncthreads();
        if (tid < 64) {
            float ii = gsh[tid], ff = gsh[64 + tid], gg = gsh[128 + tid], oo = gsh[192 + tid];
            float c  = sigmoidf_(ff) * g_cc[b * 64 + tid] + sigmoidf_(ii) * tanhf(gg);
            float h2 = sigmoidf_(oo) * tanhf(c);
            g_cc[b * 64 + tid] = c;
            g_hh[b * 64 + tid] = h2;
        }
        __syncthreads();
    }
}

// ---------------- attention ----------------
__global__ void k_att1(const int* __restrict__ batch) {
    int n = blockIdx.x * 8 + (threadIdx.x >> 5);
    int lane = threadIdx.x & 31;
    int b = batch[n];
    float v = g_out[n * D + lane] * g_hh[b * D + lane] +
              g_out[n * D + lane + 32] * g_hh[b * D + lane + 32];
#pragma unroll
    for (int off = 16; off; off >>= 1) v += __shfl_xor_sync(0xffffffffu, v, off);
    if (lane == 0) {
        g_e[n] = v;
        atomicMax(&g_segmax[b], fkey(v));
    }
}
__global__ void k_att2(const int* __restrict__ batch) {
    int n = blockIdx.x * 256 + threadIdx.x;
    if (n < NN) {
        int b = batch[n];
        float a = expf(g_e[n] - fdec(g_segmax[b]));
        g_a[n] = a;
        atomicAdd(&g_denom[b], a);
    }
}
__global__ void k_att3(const int* __restrict__ batch) {
    int g = threadIdx.x >> 6, o = threadIdx.x & 63;
    int n = blockIdx.x * 4 + g;
    int b = batch[n];
    float coeff = g_a[n] / (g_denom[b] + 1e-16f);
    atomicAdd(&g_r[b * D + o], coeff * g_out[n * D + o]);
}
__global__ void k_qstar() {
    int idx = blockIdx.x * 256 + threadIdx.x;
    int b = idx >> 7, t = idx & 127;
    g_qstar[idx] = (t < 64) ? g_hh[b * 64 + t] : g_r[b * 64 + t - 64];
}

// ---------------- output MLP ----------------
__global__ void k_final(const float* __restrict__ l1w, const float* __restrict__ l1b,
                        const float* __restrict__ l2w, const float* __restrict__ l2b,
                        float* __restrict__ y) {
    __shared__ float qs[128];
    __shared__ float y1[64];
    int b = blockIdx.x, tid = threadIdx.x;
    qs[tid] = g_qstar[b * 128 + tid];
    __syncthreads();
    if (tid < 64) {
        float acc = l1b[tid];
        const float* wr = l1w + tid * 128;
#pragma unroll 16
        for (int i = 0; i < 128; i++) acc += qs[i] * wr[i];
        y1[tid] = fmaxf(acc, 0.f) * l2w[tid];
    }
    __syncthreads();
    if (tid < 32) {
        float v = y1[tid] + y1[tid + 32];
#pragma unroll
        for (int off = 16; off; off >>= 1) v += __shfl_xor_sync(0xffffffffu, v, off);
        if (tid == 0) y[b] = v + l2b[0];
    }
}

// ---------------- launcher ----------------
extern "C" void kernel_launch(void* const* d_in, const int* in_sizes, int n_in,
                              void* d_out, int out_size) {
    const float* x        = (const float*)d_in[0];
    const int*   ei       = (const int*)d_in[1];
    const float* ea       = (const float*)d_in[2];
    const int*   batch    = (const int*)d_in[3];
    const float* lin0_w   = (const float*)d_in[4];
    const float* lin0_b   = (const float*)d_in[5];
    const float* nn_w1    = (const float*)d_in[6];
    const float* nn_b1    = (const float*)d_in[7];
    const float* nn_w2    = (const float*)d_in[8];
    const float* nn_b2    = (const float*)d_in[9];
    const float* conv_root= (const float*)d_in[10];
    const float* conv_bias= (const float*)d_in[11];
    const float* gwih     = (const float*)d_in[12];
    const float* gwhh     = (const float*)d_in[13];
    const float* gbih     = (const float*)d_in[14];
    const float* gbhh     = (const float*)d_in[15];
    const float* swih     = (const float*)d_in[16];
    const float* swhh     = (const float*)d_in[17];
    const float* sbih     = (const float*)d_in[18];
    const float* sbhh     = (const float*)d_in[19];
    const float* l1w      = (const float*)d_in[20];
    const float* l1b      = (const float*)d_in[21];
    const float* l2w      = (const float*)d_in[22];
    const float* l2b      = (const float*)d_in[23];
    float* yout = (float*)d_out;

    const int SMEM_GEMM  = 2 * 128 * LDW * 4;                                // 69632
    const int SMEM_NODE  = (4096 + 2 * 192 * 65 + 64 + 192 + 192 + 512) * 4; // 120064
    const int SMEM_LSTM  = (256 * 129 + 256 * 65 + 128 + 64 + 256) * 4;      // 200448
    cudaFuncSetAttribute(k_gemm_hmma, cudaFuncAttributeMaxDynamicSharedMemorySize, SMEM_GEMM);
    cudaFuncSetAttribute(k_node,  cudaFuncAttributeMaxDynamicSharedMemorySize, SMEM_NODE);
    cudaFuncSetAttribute(k_lstm,  cudaFuncAttributeMaxDynamicSharedMemorySize, SMEM_LSTM);

    // 1) node embedding
    k_lin0<<<NN / 4, 256>>>(x, lin0_w, lin0_b);
    // 2) degrees
    k_zero_invdeg<<<(NN + 255) / 256, 256>>>();
    k_deg<<<(NE + 255) / 256, 256>>>(ei);
    k_deg_fin<<<(NN + 255) / 256, 256>>>();
    // 3) edge network
    k_edge1<<<NE / 2, 256>>>(ea, nn_w1, nn_b1);
    k_w2conv<<<4096 * 128 / 256, 256>>>(nn_w2);
    k_gemm_hmma<<<dim3(32, (NE + 127) / 128), 256, SMEM_GEMM>>>(nn_b2);
    // 4) 3 rounds of message passing + GRU
    for (int t = 0; t < 3; t++) {
        k_zero_agg<<<NN * D / 256, 256>>>();
        k_msg<<<NE / 8, 256>>>(ei);
        k_node<<<592, 256, SMEM_NODE>>>(conv_root, conv_bias, gwih, gwhh, gbih, gbhh);
    }
    // 5) Set2Set
    k_zero_s2s<<<NB, 256>>>();
    for (int s = 0; s < 3; s++) {
        k_lstm<<<256, 256, SMEM_LSTM>>>(swih, swhh, sbih, sbhh);
        k_zero_att<<<(NB * 66 + 255) / 256, 256>>>();
        k_att1<<<NN / 8, 256>>>(batch);
        k_att2<<<(NN + 255) / 256, 256>>>(batch);
        k_att3<<<NN / 4, 256>>>(batch);
        k_qstar<<<NB * 128 / 256, 256>>>();
    }
    // 6) readout MLP
    k_final<<<NB, 128>>>(l1w, l1b, l2w, l2b, yout);
}

// round 6
// speedup vs baseline: 2.3621x; 1.2160x over previous
#include <cuda_runtime.h>
#include <cuda_bf16.h>
#include <cuda_fp16.h>
#include <math.h>
#include <stdint.h>

#define NN 50000
#define NE 100000
#define NB 2048
#define D  64

// ---------------- scratch (device globals; no allocation allowed) -------------
__device__ __align__(16) __nv_bfloat16 g_h1b[(size_t)NE * 128];
__device__ __align__(16) __nv_bfloat16 g_w2b[(size_t)4096 * 128];
__device__ __align__(16) __half g_ew[(size_t)NE * 4096];   // 0.82 GB fp16
__device__ float    g_out[NN * D];              // node state (h == out)
__device__ float    g_agg[NN * D];              // message accumulator
__device__ float    g_invdeg[NN];
__device__ float    g_e[NN];
__device__ float    g_a[NN];
__device__ unsigned g_segmax[NB];
__device__ float    g_denom[NB];
__device__ float    g_r[NB * D];
__device__ float    g_hh[NB * D];
__device__ float    g_cc[NB * D];

__device__ __forceinline__ float sigmoidf_(float x) { return 1.f / (1.f + expf(-x)); }

__device__ __forceinline__ unsigned fkey(float f) {
    unsigned b = __float_as_uint(f);
    return (b & 0x80000000u) ? ~b : (b | 0x80000000u);
}
__device__ __forceinline__ float fdec(unsigned k) {
    unsigned b = (k & 0x80000000u) ? (k ^ 0x80000000u) : ~k;
    return __uint_as_float(b);
}

// ---------------- zero kernels ----------------
__global__ void k_zero_invdeg() {
    int i = blockIdx.x * 256 + threadIdx.x;
    if (i < NN) g_invdeg[i] = 0.f;
}
__global__ void k_zero_agg() {
    int i = blockIdx.x * 256 + threadIdx.x;
    g_agg[i] = 0.f;
}
__global__ void k_zero_s2s() {
    int i = blockIdx.x * 256 + threadIdx.x;  // grid covers NB*192 exactly
    if (i < NB * 64) g_r[i] = 0.f;
    else if (i < NB * 128) g_hh[i - NB * 64] = 0.f;
    else g_cc[i - NB * 128] = 0.f;
}
__global__ void k_zero_att() {
    int i = blockIdx.x * 256 + threadIdx.x;  // covers NB*66
    if (i < NB) { g_denom[i] = 0.f; g_segmax[i] = 0u; }
    else if (i < NB + NB * 64) g_r[i - NB] = 0.f;
}

// ---------------- lin0 + relu ----------------
__global__ void k_lin0(const float* __restrict__ x, const float* __restrict__ w,
                       const float* __restrict__ b) {
    __shared__ float xs[4][14];
    int g = threadIdx.x >> 6, o = threadIdx.x & 63;
    int n = blockIdx.x * 4 + g;
    if (o < 14) xs[g][o] = x[n * 14 + o];
    __syncthreads();
    float acc = b[o];
#pragma unroll
    for (int j = 0; j < 14; j++) acc += xs[g][j] * w[o * 14 + j];
    g_out[n * D + o] = fmaxf(acc, 0.f);
}

// ---------------- degree ----------------
__global__ void k_deg(const int* __restrict__ ei) {
    int e = blockIdx.x * 256 + threadIdx.x;
    if (e < NE) atomicAdd(&g_invdeg[ei[NE + e]], 1.f);
}
__global__ void k_deg_fin() {
    int n = blockIdx.x * 256 + threadIdx.x;
    if (n < NN) g_invdeg[n] = 1.f / fmaxf(g_invdeg[n], 1.f);
}

// ---------------- edge net layer 1 (bf16 out) ----------------
__global__ void k_edge1(const float* __restrict__ ea, const float* __restrict__ w1,
                        const float* __restrict__ b1) {
    int k = threadIdx.x & 127;
    int e = blockIdx.x * 2 + (threadIdx.x >> 7);
    float a0 = ea[e * 4 + 0], a1 = ea[e * 4 + 1], a2 = ea[e * 4 + 2], a3 = ea[e * 4 + 3];
    float acc = b1[k] + a0 * w1[k * 4 + 0] + a1 * w1[k * 4 + 1] +
                a2 * w1[k * 4 + 2] + a3 * w1[k * 4 + 3];
    g_h1b[(size_t)e * 128 + k] = __float2bfloat16(fmaxf(acc, 0.f));
}

// ---------------- W2 fp32 -> bf16 ----------------
__global__ void k_w2conv(const float* __restrict__ w2) {
    int i = blockIdx.x * 256 + threadIdx.x;  // covers 4096*128
    g_w2b[i] = __float2bfloat16(w2[i]);
}

// ---------------- HMMA helper ----------------
__device__ __forceinline__ void mma_bf16(float* c, const uint32_t* a,
                                         uint32_t b0, uint32_t b1) {
    asm volatile(
        "mma.sync.aligned.m16n8k16.row.col.f32.bf16.bf16.f32 "
        "{%0,%1,%2,%3}, {%4,%5,%6,%7}, {%8,%9}, {%0,%1,%2,%3};"
        : "+f"(c[0]), "+f"(c[1]), "+f"(c[2]), "+f"(c[3])
        : "r"(a[0]), "r"(a[1]), "r"(a[2]), "r"(a[3]), "r"(b0), "r"(b1));
}

// ---------------- big GEMM on HMMA: ew = h1 @ W2^T + b2 (fp16 out) ----------
// M=1e5 (pad 128), N=4096, K=128. Single-pass bf16, fp32 accum.
// Block 128x128, 4 warps (2M x 2N), warp tile 64x64.
// SMEM word layout: [row][68 words], word = 2 bf16 (k-contiguous).
#define LDW 68
__global__ void __launch_bounds__(128, 2)
k_gemm_hmma(const float* __restrict__ b2) {
    extern __shared__ uint32_t sw[];
    uint32_t* As = sw;                 // 128*LDW
    uint32_t* Bs = As + 128 * LDW;     // 128*LDW
    const int tid = threadIdx.x;
    const int m0 = blockIdx.y * 128, n0 = blockIdx.x * 128;

    // ---- load tiles: each of 128 threads loads A row tid and B row tid
    {
        int m = m0 + tid;
        bool valid = m < NE;
        const uint4* srcA = (const uint4*)(g_h1b + (size_t)m * 128);
        const uint4* srcB = (const uint4*)(g_w2b + (size_t)(n0 + tid) * 128);
        uint32_t* dstA = As + tid * LDW;
        uint32_t* dstB = Bs + tid * LDW;
#pragma unroll
        for (int kc = 0; kc < 16; kc++) {
            uint4 va = valid ? srcA[kc] : make_uint4(0u, 0u, 0u, 0u);
            *(uint4*)(dstA + kc * 4) = va;
            *(uint4*)(dstB + kc * 4) = srcB[kc];
        }
    }
    __syncthreads();

    const int wid = tid >> 5, lane = tid & 31;
    const int warpM = wid >> 1, warpN = wid & 1;
    const int g = lane >> 2, tg = lane & 3;

    float c[4][8][4];
#pragma unroll
    for (int mi = 0; mi < 4; mi++)
#pragma unroll
        for (int ni = 0; ni < 8; ni++)
#pragma unroll
            for (int q = 0; q < 4; q++) c[mi][ni][q] = 0.f;

#pragma unroll
    for (int s = 0; s < 8; s++) {
        const int kw = s * 8 + tg;
        uint32_t a[4][4];
#pragma unroll
        for (int mi = 0; mi < 4; mi++) {
            const uint32_t* ar = As + (warpM * 64 + mi * 16 + g) * LDW;
            a[mi][0] = ar[kw];
            a[mi][1] = ar[8 * LDW + kw];
            a[mi][2] = ar[kw + 4];
            a[mi][3] = ar[8 * LDW + kw + 4];
        }
#pragma unroll
        for (int ni = 0; ni < 8; ni++) {
            const uint32_t* br = Bs + (warpN * 64 + ni * 8 + g) * LDW;
            uint32_t b0 = br[kw], b1 = br[kw + 4];
#pragma unroll
            for (int mi = 0; mi < 4; mi++) mma_bf16(c[mi][ni], a[mi], b0, b1);
        }
    }

    // ---- epilogue: bias + convert to fp16 + store
    {
        const int colbase = n0 + warpN * 64 + 2 * tg;
        float2 bias[8];
#pragma unroll
        for (int ni = 0; ni < 8; ni++)
            bias[ni] = *(const float2*)(b2 + colbase + ni * 8);
#pragma unroll
        for (int mi = 0; mi < 4; mi++) {
            int r0 = m0 + warpM * 64 + mi * 16 + g;
            if (r0 < NE) {
                __half2* rp = (__half2*)(g_ew + (size_t)r0 * 4096 + colbase);
#pragma unroll
                for (int ni = 0; ni < 8; ni++)
                    rp[ni * 4] = __floats2half2_rn(c[mi][ni][0] + bias[ni].x,
                                                   c[mi][ni][1] + bias[ni].y);
            }
            int r1 = r0 + 8;
            if (r1 < NE) {
                __half2* rp = (__half2*)(g_ew + (size_t)r1 * 4096 + colbase);
#pragma unroll
                for (int ni = 0; ni < 8; ni++)
                    rp[ni * 4] = __floats2half2_rn(c[mi][ni][2] + bias[ni].x,
                                                   c[mi][ni][3] + bias[ni].y);
            }
        }
    }
}

// ---------------- per-edge matvec + scatter (one warp per edge) -------------
__global__ void k_msg(const int* __restrict__ ei) {
    __shared__ float so[8][64];
    int g = threadIdx.x >> 5, o2 = threadIdx.x & 31;
    int e = blockIdx.x * 8 + g;
    int s = ei[e], d = ei[NE + e];
    *(float2*)&so[g][o2 * 2] = *(const float2*)(g_out + s * D + o2 * 2);
    __syncwarp();
    const __half2* ewp = (const __half2*)g_ew + (size_t)e * 2048 + o2;
    float ax = 0.f, ay = 0.f;
#pragma unroll 16
    for (int i = 0; i < 64; i++) {
        float2 w = __half22float2(__ldg(ewp + i * 32));
        float sv = so[g][i];
        ax += sv * w.x;
        ay += sv * w.y;
    }
    atomicAdd(&g_agg[d * D + 2 * o2], ax);
    atomicAdd(&g_agg[d * D + 2 * o2 + 1], ay);
}

// ---------------- fused conv_root + GRU (4 nodes/thread, 16 nodes/iter) ----
// grid = 625 blocks: 625*16*5 = 50000 exactly (no bounds checks needed)
__global__ void k_node(const float* __restrict__ root, const float* __restrict__ cbias,
                       const float* __restrict__ wih, const float* __restrict__ whh,
                       const float* __restrict__ bih, const float* __restrict__ bhh) {
    extern __shared__ float sm[];
    float* root_s = sm;                 // 4096
    float* wih_s  = sm + 4096;          // 192*65
    float* whh_s  = wih_s + 192 * 65;
    float* cb_s   = whh_s + 192 * 65;   // 64
    float* bih_s  = cb_s + 64;          // 192
    float* bhh_s  = bih_s + 192;        // 192
    float* orow   = bhh_s + 192;        // 16*64
    float* mrow   = orow + 1024;        // 16*64
    int tid = threadIdx.x;
    for (int i = tid; i < 4096; i += 256) root_s[i] = root[i];
    for (int i = tid; i < 192 * 64; i += 256) {
        int rr = i >> 6, cc = i & 63;
        wih_s[rr * 65 + cc] = wih[i];
        whh_s[rr * 65 + cc] = whh[i];
    }
    if (tid < 64) cb_s[tid] = cbias[tid];
    if (tid < 192) { bih_s[tid] = bih[tid]; bhh_s[tid] = bhh[tid]; }
    __syncthreads();
    const int q = tid >> 6, o = tid & 63;
    const float* w0 = wih_s + o * 65;
    const float* w1 = wih_s + (64 + o) * 65;
    const float* w2 = wih_s + (128 + o) * 65;
    const float* v0 = whh_s + o * 65;
    const float* v1 = whh_s + (64 + o) * 65;
    const float* v2 = whh_s + (128 + o) * 65;

    for (int base = blockIdx.x * 16; base < NN; base += gridDim.x * 16) {
        float h[4], m[4];
#pragma unroll
        for (int j = 0; j < 4; j++) {
            int n = base + j * 4 + q;
            h[j] = g_out[n * D + o];
            orow[(j * 4 + q) * 64 + o] = h[j];
            m[j] = cb_s[o] + g_agg[n * D + o] * g_invdeg[n];
            g_agg[n * D + o] = 0.f;  // pre-zero for next round
        }
        __syncthreads();
#pragma unroll 8
        for (int i = 0; i < 64; i++) {
            float rv = root_s[i * 64 + o];
#pragma unroll
            for (int j = 0; j < 4; j++) m[j] += orow[(j * 4 + q) * 64 + i] * rv;
        }
#pragma unroll
        for (int j = 0; j < 4; j++) {
            m[j] = fmaxf(m[j], 0.f);
            mrow[(j * 4 + q) * 64 + o] = m[j];
        }
        __syncthreads();
        float gi0[4], gi1[4], gi2[4], gh0[4], gh1[4], gh2[4];
#pragma unroll
        for (int j = 0; j < 4; j++) {
            gi0[j] = bih_s[o]; gi1[j] = bih_s[64 + o]; gi2[j] = bih_s[128 + o];
            gh0[j] = bhh_s[o]; gh1[j] = bhh_s[64 + o]; gh2[j] = bhh_s[128 + o];
        }
#pragma unroll 4
        for (int i = 0; i < 64; i++) {
            float w0i = w0[i], w1i = w1[i], w2i = w2[i];
            float v0i = v0[i], v1i = v1[i], v2i = v2[i];
#pragma unroll
            for (int j = 0; j < 4; j++) {
                float mi = mrow[(j * 4 + q) * 64 + i];
                float hi = orow[(j * 4 + q) * 64 + i];
                gi0[j] += mi * w0i; gi1[j] += mi * w1i; gi2[j] += mi * w2i;
                gh0[j] += hi * v0i; gh1[j] += hi * v1i; gh2[j] += hi * v2i;
            }
        }
#pragma unroll
        for (int j = 0; j < 4; j++) {
            float r  = sigmoidf_(gi0[j] + gh0[j]);
            float z  = sigmoidf_(gi1[j] + gh1[j]);
            float nn = tanhf(gi2[j] + r * gh2[j]);
            float hn = (1.f - z) * nn + z * h[j];
            int n = base + j * 4 + q;
            g_out[n * D + o] = hn;
        }
        __syncthreads();
    }
}

// ---------------- Set2Set LSTM cell (reads [hh, r] directly) ----------------
__global__ void k_lstm(const float* __restrict__ wih, const float* __restrict__ whh,
                       const float* __restrict__ bih, const float* __restrict__ bhh) {
    extern __shared__ float sm[];
    float* wih_s = sm;                   // 256*129
    float* whh_s = wih_s + 256 * 129;    // 256*65
    float* qs    = whh_s + 256 * 65;     // 128
    float* hs    = qs + 128;             // 64
    float* gsh   = hs + 64;              // 256
    int tid = threadIdx.x;
    for (int i = tid; i < 256 * 128; i += 256) {
        int rr = i >> 7, cc = i & 127;
        wih_s[rr * 129 + cc] = wih[i];
    }
    for (int i = tid; i < 256 * 64; i += 256) {
        int rr = i >> 6, cc = i & 63;
        whh_s[rr * 65 + cc] = whh[i];
    }
    float bsum = bih[tid] + bhh[tid];
    __syncthreads();
    for (int it = 0; it < 8; it++) {
        int b = blockIdx.x + 256 * it;
        if (tid < 64) { qs[tid] = g_hh[b * 64 + tid]; hs[tid] = g_hh[b * 64 + tid]; }
        else if (tid < 128) qs[tid] = g_r[b * 64 + tid - 64];
        __syncthreads();
        float acc = bsum;
        const float* wr = wih_s + tid * 129;
#pragma unroll 16
        for (int i = 0; i < 128; i++) acc += qs[i] * wr[i];
        const float* vr = whh_s + tid * 65;
#pragma unroll 16
        for (int i = 0; i < 64; i++) acc += hs[i] * vr[i];
        gsh[tid] = acc;
        __syncthreads();
        if (tid < 64) {
            float ii = gsh[tid], ff = gsh[64 + tid], gg = gsh[128 + tid], oo = gsh[192 + tid];
            float c  = sigmoidf_(ff) * g_cc[b * 64 + tid] + sigmoidf_(ii) * tanhf(gg);
            float h2 = sigmoidf_(oo) * tanhf(c);
            g_cc[b * 64 + tid] = c;
            g_hh[b * 64 + tid] = h2;
        }
        __syncthreads();
    }
}

// ---------------- attention ----------------
__global__ void k_att1(const int* __restrict__ batch) {
    int n = blockIdx.x * 8 + (threadIdx.x >> 5);
    int lane = threadIdx.x & 31;
    int b = batch[n];
    float v = g_out[n * D + lane] * g_hh[b * D + lane] +
              g_out[n * D + lane + 32] * g_hh[b * D + lane + 32];
#pragma unroll
    for (int off = 16; off; off >>= 1) v += __shfl_xor_sync(0xffffffffu, v, off);
    if (lane == 0) {
        g_e[n] = v;
        atomicMax(&g_segmax[b], fkey(v));
    }
}
__global__ void k_att2(const int* __restrict__ batch) {
    int n = blockIdx.x * 256 + threadIdx.x;
    if (n < NN) {
        int b = batch[n];
        float a = expf(g_e[n] - fdec(g_segmax[b]));
        g_a[n] = a;
        atomicAdd(&g_denom[b], a);
    }
}
__global__ void k_att3(const int* __restrict__ batch) {
    int g = threadIdx.x >> 6, o = threadIdx.x & 63;
    int n = blockIdx.x * 4 + g;
    int b = batch[n];
    float coeff = g_a[n] / (g_denom[b] + 1e-16f);
    atomicAdd(&g_r[b * D + o], coeff * g_out[n * D + o]);
}

// ---------------- output MLP (reads [hh, r]) ----------------
__global__ void k_final(const float* __restrict__ l1w, const float* __restrict__ l1b,
                        const float* __restrict__ l2w, const float* __restrict__ l2b,
                        float* __restrict__ y) {
    __shared__ float qs[128];
    __shared__ float y1[64];
    int b = blockIdx.x, tid = threadIdx.x;
    qs[tid] = (tid < 64) ? g_hh[b * 64 + tid] : g_r[b * 64 + tid - 64];
    __syncthreads();
    if (tid < 64) {
        float acc = l1b[tid];
        const float* wr = l1w + tid * 128;
#pragma unroll 16
        for (int i = 0; i < 128; i++) acc += qs[i] * wr[i];
        y1[tid] = fmaxf(acc, 0.f) * l2w[tid];
    }
    __syncthreads();
    if (tid < 32) {
        float v = y1[tid] + y1[tid + 32];
#pragma unroll
        for (int off = 16; off; off >>= 1) v += __shfl_xor_sync(0xffffffffu, v, off);
        if (tid == 0) y[b] = v + l2b[0];
    }
}

// ---------------- launcher ----------------
extern "C" void kernel_launch(void* const* d_in, const int* in_sizes, int n_in,
                              void* d_out, int out_size) {
    const float* x        = (const float*)d_in[0];
    const int*   ei       = (const int*)d_in[1];
    const float* ea       = (const float*)d_in[2];
    const int*   batch    = (const int*)d_in[3];
    const float* lin0_w   = (const float*)d_in[4];
    const float* lin0_b   = (const float*)d_in[5];
    const float* nn_w1    = (const float*)d_in[6];
    const float* nn_b1    = (const float*)d_in[7];
    const float* nn_w2    = (const float*)d_in[8];
    const float* nn_b2    = (const float*)d_in[9];
    const float* conv_root= (const float*)d_in[10];
    const float* conv_bias= (const float*)d_in[11];
    const float* gwih     = (const float*)d_in[12];
    const float* gwhh     = (const float*)d_in[13];
    const float* gbih     = (const float*)d_in[14];
    const float* gbhh     = (const float*)d_in[15];
    const float* swih     = (const float*)d_in[16];
    const float* swhh     = (const float*)d_in[17];
    const float* sbih     = (const float*)d_in[18];
    const float* sbhh     = (const float*)d_in[19];
    const float* l1w      = (const float*)d_in[20];
    const float* l1b      = (const float*)d_in[21];
    const float* l2w      = (const float*)d_in[22];
    const float* l2b      = (const float*)d_in[23];
    float* yout = (float*)d_out;

    const int SMEM_GEMM  = 2 * 128 * LDW * 4;                                 // 69632
    const int SMEM_NODE  = (4096 + 2 * 192 * 65 + 64 + 192 + 192 + 2048) * 4; // 126208
    const int SMEM_LSTM  = (256 * 129 + 256 * 65 + 128 + 64 + 256) * 4;       // 200448
    cudaFuncSetAttribute(k_gemm_hmma, cudaFuncAttributeMaxDynamicSharedMemorySize, SMEM_GEMM);
    cudaFuncSetAttribute(k_node,  cudaFuncAttributeMaxDynamicSharedMemorySize, SMEM_NODE);
    cudaFuncSetAttribute(k_lstm,  cudaFuncAttributeMaxDynamicSharedMemorySize, SMEM_LSTM);

    // 1) node embedding
    k_lin0<<<NN / 4, 256>>>(x, lin0_w, lin0_b);
    // 2) degrees
    k_zero_invdeg<<<(NN + 255) / 256, 256>>>();
    k_deg<<<(NE + 255) / 256, 256>>>(ei);
    k_deg_fin<<<(NN + 255) / 256, 256>>>();
    // 3) edge network
    k_edge1<<<NE / 2, 256>>>(ea, nn_w1, nn_b1);
    k_w2conv<<<4096 * 128 / 256, 256>>>(nn_w2);
    k_gemm_hmma<<<dim3(32, (NE + 127) / 128), 128, SMEM_GEMM>>>(nn_b2);
    // 4) 3 rounds of message passing + GRU (k_node re-zeros agg for next round)
    k_zero_agg<<<NN * D / 256, 256>>>();
    for (int t = 0; t < 3; t++) {
        k_msg<<<NE / 8, 256>>>(ei);
        k_node<<<625, 256, SMEM_NODE>>>(conv_root, conv_bias, gwih, gwhh, gbih, gbhh);
    }
    // 5) Set2Set
    k_zero_s2s<<<NB * 192 / 256, 256>>>();
    for (int s = 0; s < 3; s++) {
        k_lstm<<<256, 256, SMEM_LSTM>>>(swih, swhh, sbih, sbhh);
        k_zero_att<<<(NB * 66 + 255) / 256, 256>>>();
        k_att1<<<NN / 8, 256>>>(batch);
        k_att2<<<(NN + 255) / 256, 256>>>(batch);
        k_att3<<<NN / 4, 256>>>(batch);
    }
    // 6) readout MLP
    k_final<<<NB, 128>>>(l1w, l1b, l2w, l2b, yout);
}